// round 3
// baseline (speedup 1.0000x reference)
#include <cuda_runtime.h>
#include <math.h>

#define HW 96
#define P  (96*96)          // 9216
#define BB 4
#define KK7 7
#define CC 64
#define CAT 448
#define HEAD 256

// ---------------- scratch (device globals; no allocation allowed) ----------------
__device__ float g_cat [BB*CAT*P];           // 16.5M
__device__ float g_wh1 [28*HEAD*P];          // 66.1M
__device__ float g_hm1 [BB*HEAD*P];          // 9.4M
__device__ float g_id1 [BB*HEAD*P];          // 9.4M
__device__ float g_off [BB*189*P];           // 7.0M
__device__ float g_cols[BB*4032*P];          // 148.6M
__device__ float g_wre [HEAD*4032];          // 1.0M
__device__ float g_d   [BB*HEAD*P];          // 9.4M  (post BN+relu)

// ---------------- build cat: (B, K*C, H, W) from features (K,B,C,H,W) -------------
__global__ __launch_bounds__(256) void build_cat_k(const float* __restrict__ feat,
                                                   float* __restrict__ cat) {
    int idx = blockIdx.x * 256 + threadIdx.x;     // grid exact
    int p  = idx % P;
    int t  = idx / P;         // b*448 + kc
    int kc = t % CAT;
    int b  = t / CAT;
    int k  = kc >> 6, c = kc & 63;
    cat[idx] = feat[(((k*BB)+b)*CC + c)*P + p];
}

// ---------------- generic conv3x3 (pad 1): 64-oc x 96-px row tile ----------------
// grid (ocTiles, 96, nImages), block 256. Cin % 8 == 0.
__global__ __launch_bounds__(256) void conv3x3_k(const float* __restrict__ in,
                                                 const float* __restrict__ w,
                                                 const float* __restrict__ bias,
                                                 float* __restrict__ out,
                                                 int Cin, int Cout, int relu) {
    const int ICC = 8;
    __shared__ float s_in[ICC][3][HW+2];   // 8*3*98 floats
    __shared__ float s_w [64][ICC*9 + 1];  // stride 73 (conflict-free)
    int tid = threadIdx.x;
    int tx = tid & 15;        // pixel group: x = tx*6 .. tx*6+5
    int ty = tid >> 4;        // oc group:  oc = ocBase + ty*4 .. +3
    int y  = blockIdx.y;
    int n  = blockIdx.z;
    int ocBase = blockIdx.x * 64;
    const float* inN = in + (long)n * Cin * P;

    float acc[4][6];
#pragma unroll
    for (int o=0;o<4;o++)
#pragma unroll
        for (int j=0;j<6;j++) acc[o][j]=0.f;

    for (int ic0 = 0; ic0 < Cin; ic0 += ICC) {
        // stage input: ICC ch x 3 rows x 98 (zero-padded halo)
        for (int idx = tid; idx < ICC*3*(HW+2); idx += 256) {
            int xx  = idx % (HW+2);
            int rem = idx / (HW+2);
            int ry  = rem % 3;
            int ci  = rem / 3;
            int gy = y - 1 + ry;
            int gx = xx - 1;
            float v = 0.f;
            if (gy >= 0 && gy < HW && gx >= 0 && gx < HW)
                v = inN[(ic0 + ci) * P + gy*HW + gx];
            s_in[ci][ry][xx] = v;
        }
        // stage weights: 64 oc x ICC x 9
        for (int idx = tid; idx < 64*ICC*9; idx += 256) {
            int t = idx % (ICC*9);
            int o = idx / (ICC*9);
            int oc = ocBase + o;
            float v = 0.f;
            if (oc < Cout) {
                int ci = t / 9, tap = t % 9;
                v = w[((long)oc*Cin + ic0+ci)*9 + tap];
            }
            s_w[o][t] = v;
        }
        __syncthreads();
#pragma unroll 2
        for (int ci = 0; ci < ICC; ci++) {
#pragma unroll
            for (int ky = 0; ky < 3; ky++) {
                float iv[8];
#pragma unroll
                for (int j = 0; j < 8; j++) iv[j] = s_in[ci][ky][tx*6 + j];
#pragma unroll
                for (int kx = 0; kx < 3; kx++) {
                    float wv[4];
#pragma unroll
                    for (int o = 0; o < 4; o++) wv[o] = s_w[ty*4+o][ci*9 + ky*3 + kx];
#pragma unroll
                    for (int o = 0; o < 4; o++)
#pragma unroll
                        for (int j = 0; j < 6; j++)
                            acc[o][j] += wv[o] * iv[j+kx];
                }
            }
        }
        __syncthreads();
    }
#pragma unroll
    for (int o = 0; o < 4; o++) {
        int oc = ocBase + ty*4 + o;
        if (oc < Cout) {
            float bv = bias[oc];
#pragma unroll
            for (int j = 0; j < 6; j++) {
                float v = acc[o][j] + bv;
                if (relu) v = fmaxf(v, 0.f);
                out[((long)n*Cout + oc)*P + y*HW + tx*6 + j] = v;
            }
        }
    }
}

// ---------------- DCN: reorder weights (oc, g, c, kk) -> (oc, (g*9+kk)*64+c) ------
__global__ __launch_bounds__(256) void reorder_w_k(const float* __restrict__ dcn_w,
                                                   float* __restrict__ wre) {
    int idx = blockIdx.x * 256 + threadIdx.x;   // 256*4032 exact
    int oc = idx / 4032;
    int t  = idx % 4032;
    int g  = t / 576;
    int r  = t % 576;
    int kk = r / 64;
    int c  = r % 64;
    wre[idx] = dcn_w[((long)oc*CAT + g*64 + c)*9 + kk];
}

// ---------------- DCN: bilinear gather into cols (b, gk, c, p) --------------------
// grid (36, 63, 4), block 256
__global__ __launch_bounds__(256) void dcn_cols_k(const float* __restrict__ cat,
                                                  const float* __restrict__ off,
                                                  float* __restrict__ cols) {
    int p  = blockIdx.x * 256 + threadIdx.x;
    int gk = blockIdx.y;
    int b  = blockIdx.z;
    int yy = p / HW, xx = p % HW;
    const float* ob = off + (long)b*189*P + p;
    float oy = ob[gk*P];
    float ox = ob[(63+gk)*P];
    float m  = ob[(126+gk)*P];
    m = 1.f / (1.f + expf(-m));
    int kk = gk % 9;
    float sy = (float)(yy - 1 + kk/3) + oy;
    float sx = (float)(xx - 1 + kk%3) + ox;
    float y0f = floorf(sy), x0f = floorf(sx);
    float wy = sy - y0f, wx = sx - x0f;
    int y0 = (int)y0f, x0 = (int)x0f;
    int y1 = y0 + 1, x1 = x0 + 1;
    bool vy0 = (y0>=0)&&(y0<HW), vy1 = (y1>=0)&&(y1<HW);
    bool vx0 = (x0>=0)&&(x0<HW), vx1 = (x1>=0)&&(x1<HW);
    int cy0 = min(max(y0,0),HW-1), cy1 = min(max(y1,0),HW-1);
    int cx0 = min(max(x0,0),HW-1), cx1 = min(max(x1,0),HW-1);
    float w00 = (vy0&&vx0) ? (1.f-wy)*(1.f-wx)*m : 0.f;
    float w01 = (vy0&&vx1) ? (1.f-wy)*wx*m       : 0.f;
    float w10 = (vy1&&vx0) ? wy*(1.f-wx)*m       : 0.f;
    float w11 = (vy1&&vx1) ? wy*wx*m             : 0.f;
    int i00 = cy0*HW+cx0, i01 = cy0*HW+cx1, i10 = cy1*HW+cx0, i11 = cy1*HW+cx1;
    int g = gk / 9;
    const float* xb = cat + (long)(b*CAT + g*64)*P;
    float* cb = cols + ((long)(b*63 + gk))*64*P + p;
#pragma unroll 4
    for (int c = 0; c < 64; c++) {
        const float* xc = xb + c*P;
        float v = w00*xc[i00] + w01*xc[i01] + w10*xc[i10] + w11*xc[i11];
        cb[c*P] = v;
    }
}

// ---------------- DCN GEMM: d[b] = Wre(256x4032) @ cols[b](4032x9216), fused
// +bias, BN, relu.  grid (2, 96, 4), block 256, 128-oc tile.
__global__ __launch_bounds__(256) void dcn_gemm_k(const float* __restrict__ in,
                                                  const float* __restrict__ w,
                                                  const float* __restrict__ bias,
                                                  const float* __restrict__ gamma,
                                                  const float* __restrict__ beta,
                                                  const float* __restrict__ mean,
                                                  const float* __restrict__ var,
                                                  float* __restrict__ out) {
    __shared__ float s_in[16][HW];
    __shared__ float s_w [128][17];
    int tid = threadIdx.x;
    int tx = tid & 15, ty = tid >> 4;
    int y = blockIdx.y, b = blockIdx.z;
    int ocBase = blockIdx.x * 128;
    const float* inb = in + (long)b*4032*P + y*HW;
    float acc[8][6];
#pragma unroll
    for (int o=0;o<8;o++)
#pragma unroll
        for (int j=0;j<6;j++) acc[o][j]=0.f;

    for (int k0 = 0; k0 < 4032; k0 += 16) {
        for (int idx = tid; idx < 16*HW; idx += 256) {
            int ci = idx / HW, xx = idx % HW;
            s_in[ci][xx] = inb[(long)(k0+ci)*P + xx];
        }
        for (int idx = tid; idx < 128*16; idx += 256) {
            int o = idx >> 4, ci = idx & 15;
            s_w[o][ci] = w[(long)(ocBase+o)*4032 + k0 + ci];
        }
        __syncthreads();
#pragma unroll 2
        for (int ci = 0; ci < 16; ci++) {
            float iv[6];
#pragma unroll
            for (int j=0;j<6;j++) iv[j] = s_in[ci][tx*6+j];
            float wv[8];
#pragma unroll
            for (int o=0;o<8;o++) wv[o] = s_w[ty*8+o][ci];
#pragma unroll
            for (int o=0;o<8;o++)
#pragma unroll
                for (int j=0;j<6;j++) acc[o][j] += wv[o]*iv[j];
        }
        __syncthreads();
    }
#pragma unroll
    for (int o=0;o<8;o++) {
        int oc = ocBase + ty*8 + o;
        float sc = gamma[oc] * rsqrtf(var[oc] + 1e-5f);
        float bb = bias[oc] - mean[oc];
        float bt = beta[oc];
#pragma unroll
        for (int j=0;j<6;j++) {
            float v = (acc[o][j] + bb) * sc + bt;
            out[((long)b*HEAD + oc)*P + y*HW + tx*6 + j] = fmaxf(v, 0.f);
        }
    }
}

// ---------------- conv1x1 (Cin=256), OCT out channels per block ------------------
// grid (18, nImages, Cout/OCT), block 256, 2 px/thread.
// owh_mode: scatter out[((n%4)*14 + (n/4)*2 + oc)*P + px]
template<int OCT>
__global__ __launch_bounds__(256) void conv1x1_k(const float* __restrict__ in,
                                                 const float* __restrict__ w,
                                                 const float* __restrict__ bias,
                                                 float* __restrict__ out,
                                                 int Cout, int owh_mode) {
    const int Cin = 256;
    __shared__ float s_w[OCT*Cin];
    int tid = threadIdx.x;
    int n = blockIdx.y;
    int ocBase = blockIdx.z * OCT;
    for (int idx = tid; idx < OCT*Cin; idx += 256)
        s_w[idx] = w[(long)(ocBase + idx / Cin)*Cin + (idx % Cin)];
    __syncthreads();
    int px = blockIdx.x * 512 + tid * 2;
    const float* inp = in + (long)n*Cin*P + px;
    float2 acc[OCT];
#pragma unroll
    for (int o=0;o<OCT;o++) acc[o] = make_float2(0.f, 0.f);
#pragma unroll 4
    for (int ic = 0; ic < Cin; ic++) {
        float2 v = *(const float2*)(inp + (long)ic*P);
#pragma unroll
        for (int o=0;o<OCT;o++) {
            float wv = s_w[o*Cin + ic];
            acc[o].x += wv * v.x;
            acc[o].y += wv * v.y;
        }
    }
#pragma unroll
    for (int o=0;o<OCT;o++) {
        int oc = ocBase + o;
        float bv = bias[oc];
        float2 r = make_float2(acc[o].x + bv, acc[o].y + bv);
        long oidx;
        if (owh_mode) { int b = n & 3, k = n >> 2; oidx = (long)(b*14 + k*2 + oc)*P + px; }
        else          { oidx = ((long)n*Cout + oc)*P + px; }
        *(float2*)(out + oidx) = r;
    }
}

// -------------------------------- launch -----------------------------------------
extern "C" void kernel_launch(void* const* d_in, const int* in_sizes, int n_in,
                              void* d_out, int out_size) {
    const float* feat    = (const float*)d_in[0];
    const float* hm_w1   = (const float*)d_in[1];
    const float* hm_b1   = (const float*)d_in[2];
    const float* hm_w2   = (const float*)d_in[3];
    const float* hm_b2   = (const float*)d_in[4];
    const float* wh_w1   = (const float*)d_in[5];
    const float* wh_b1   = (const float*)d_in[6];
    const float* wh_w2   = (const float*)d_in[7];
    const float* wh_b2   = (const float*)d_in[8];
    const float* id_w1   = (const float*)d_in[9];
    const float* id_b1   = (const float*)d_in[10];
    const float* id_w2   = (const float*)d_in[11];
    const float* id_b2   = (const float*)d_in[12];
    const float* off_w   = (const float*)d_in[13];
    const float* off_b   = (const float*)d_in[14];
    const float* dcn_w   = (const float*)d_in[15];
    const float* dcn_b   = (const float*)d_in[16];
    const float* bn_g    = (const float*)d_in[17];
    const float* bn_b    = (const float*)d_in[18];
    const float* bn_m    = (const float*)d_in[19];
    const float* bn_v    = (const float*)d_in[20];
    const float* bz_w    = (const float*)d_in[21];
    const float* bz_b    = (const float*)d_in[22];
    float* out = (float*)d_out;

    void *p_cat, *p_wh1, *p_hm1, *p_id1, *p_off, *p_cols, *p_wre, *p_d;
    cudaGetSymbolAddress(&p_cat,  g_cat);
    cudaGetSymbolAddress(&p_wh1,  g_wh1);
    cudaGetSymbolAddress(&p_hm1,  g_hm1);
    cudaGetSymbolAddress(&p_id1,  g_id1);
    cudaGetSymbolAddress(&p_off,  g_off);
    cudaGetSymbolAddress(&p_cols, g_cols);
    cudaGetSymbolAddress(&p_wre,  g_wre);
    cudaGetSymbolAddress(&p_d,    g_d);
    float* cat  = (float*)p_cat;
    float* wh1  = (float*)p_wh1;
    float* hm1  = (float*)p_hm1;
    float* id1  = (float*)p_id1;
    float* offv = (float*)p_off;
    float* cols = (float*)p_cols;
    float* wre  = (float*)p_wre;
    float* dv   = (float*)p_d;

    // cat = features transposed to (B, K*C, H, W)
    build_cat_k<<<(BB*CAT*P)/256, 256>>>(feat, cat);

    // conv3x3 branches
    conv3x3_k<<<dim3(4, HW, 28), 256>>>(feat, wh_w1, wh_b1, wh1, CC, HEAD, 1);
    conv3x3_k<<<dim3(4, HW, 4),  256>>>(feat + 3*BB*CC*P, hm_w1, hm_b1, hm1, CC, HEAD, 1);
    conv3x3_k<<<dim3(4, HW, 4),  256>>>(cat, id_w1, id_b1, id1, CAT, HEAD, 1);
    conv3x3_k<<<dim3(3, HW, 4),  256>>>(cat, off_w, off_b, offv, CAT, 189, 0);

    // DCN
    reorder_w_k<<<(HEAD*4032)/256, 256>>>(dcn_w, wre);
    dcn_cols_k<<<dim3(P/256, 63, BB), 256>>>(cat, offv, cols);
    dcn_gemm_k<<<dim3(2, HW, BB), 256>>>(cols, wre, dcn_b, bn_g, bn_b, bn_m, bn_v, dv);

    // 1x1 heads -> output regions (hm, bz, idout, owh)
    float* out_hm  = out;
    float* out_bz  = out + (long)BB*24*P;                   // 884736
    float* out_id  = out_bz + (long)BB*16*P;                // +589824
    float* out_owh = out_id + (long)BB*128*P;               // +4718592

    conv1x1_k<24><<<dim3(18, BB, 1), 256>>>(hm1, hm_w2, hm_b2, out_hm, 24, 0);
    conv1x1_k<16><<<dim3(18, BB, 1), 256>>>(dv,  bz_w,  bz_b,  out_bz, 16, 0);
    conv1x1_k<32><<<dim3(18, BB, 4), 256>>>(id1, id_w2, id_b2, out_id, 128, 0);
    conv1x1_k<2> <<<dim3(18, 28, 1), 256>>>(wh1, wh_w2, wh_b2, out_owh, 2, 1);
}

// round 5
// speedup vs baseline: 1.2213x; 1.2213x over previous
#include <cuda_runtime.h>
#include <math.h>

#define HW 96
#define P  (96*96)          // 9216
#define BB 4
#define CC 64
#define CAT 448
#define HEAD 256

typedef unsigned long long u64;

// ---------------- f32x2 packed helpers -------------------------------------------
__device__ __forceinline__ u64 pack2(float a, float b) {
    u64 r;
    asm("mov.b64 %0, {%1, %2};" : "=l"(r)
        : "r"(__float_as_uint(a)), "r"(__float_as_uint(b)));
    return r;
}
__device__ __forceinline__ u64 ffma2(u64 a, u64 b, u64 c) {
    u64 d;
    asm("fma.rn.f32x2 %0, %1, %2, %3;" : "=l"(d) : "l"(a), "l"(b), "l"(c));
    return d;
}
__device__ __forceinline__ float2 unpk(u64 v) {
    unsigned lo, hi;
    asm("mov.b64 {%0, %1}, %2;" : "=r"(lo), "=r"(hi) : "l"(v));
    return make_float2(__uint_as_float(lo), __uint_as_float(hi));
}

// ---------------- scratch (device globals; no allocation allowed) ----------------
__device__ float g_cat [BB*CAT*P];
__device__ float g_wh1 [28*HEAD*P];
__device__ float g_hm1 [BB*HEAD*P];
__device__ float g_id1 [BB*HEAD*P];
__device__ float g_off [BB*189*P];
__device__ float g_cols[BB*4032*P];
__device__ float g_d   [BB*HEAD*P];
__device__ float g_wr_hm [CC*9*HEAD];
__device__ float g_wr_wh [CC*9*HEAD];
__device__ float g_wr_id [CAT*9*HEAD];
__device__ float g_wr_off[CAT*9*189];
__device__ float g_wre2  [4032*HEAD];

// ---------------- build cat: (B, K*C, H, W) from features (K,B,C,H,W) ------------
__global__ __launch_bounds__(256) void build_cat_k(const float* __restrict__ feat,
                                                   float* __restrict__ cat) {
    int idx = blockIdx.x * 256 + threadIdx.x;
    int p  = idx % P;
    int t  = idx / P;
    int kc = t % CAT;
    int b  = t / CAT;
    int k  = kc >> 6, c = kc & 63;
    cat[idx] = feat[(((k*BB)+b)*CC + c)*P + p];
}

// ---------------- conv weight reorder: w[oc][c][tap] -> wr[(c*9+tap)][oc] --------
__global__ __launch_bounds__(256) void reorder_conv_w_k(const float* __restrict__ w,
                                                        float* __restrict__ wr,
                                                        int Cin, int Cout) {
    int idx = blockIdx.x * 256 + threadIdx.x;
    int total = Cin * 9 * Cout;
    if (idx >= total) return;
    int oc = idx % Cout;
    int r  = idx / Cout;         // c*9+tap
    int tap = r % 9, c = r / 9;
    wr[idx] = w[((long)oc*Cin + c)*9 + tap];
}

// ---------------- DCN weight reorder: -> wre2[(g*9+kk)*64+c][oc] -----------------
__global__ __launch_bounds__(256) void reorder_dcn_w_k(const float* __restrict__ dcn_w,
                                                       float* __restrict__ wre2) {
    int idx = blockIdx.x * 256 + threadIdx.x;   // 4032*256 exact
    int oc = idx % HEAD;
    int t  = idx / HEAD;
    int g  = t / 576;
    int r  = t % 576;
    int kk = r / 64;
    int c  = r % 64;
    wre2[idx] = dcn_w[((long)oc*CAT + g*64 + c)*9 + kk];
}

// ---------------- conv3x3 pad1, f32x2 packed: 128-oc x 96-px row tile ------------
// grid (ceil(Cout/128), 96, nImages), block 256. Cin % 8 == 0.
// wr is the reordered weight buffer [(c*9+tap)][Cout].
__global__ __launch_bounds__(256) void conv3x3f2_k(const float* __restrict__ in,
                                                   const float* __restrict__ wr,
                                                   const float* __restrict__ bias,
                                                   float* __restrict__ out,
                                                   int Cin, int Cout, int relu) {
    __shared__ float s_in[8][3][HW+2];    // 9408 B
    __shared__ float s_w [72][128];       // 36864 B
    int tid = threadIdx.x;
    int tx = tid & 15;        // px base tx*6
    int ty = tid >> 4;        // oc base ty*8
    int y  = blockIdx.y;
    int n  = blockIdx.z;
    int ocBase = blockIdx.x * 128;
    const float* inN = in + (long)n * Cin * P;

    u64 acc[4][6];
#pragma unroll
    for (int q=0;q<4;q++)
#pragma unroll
        for (int j=0;j<6;j++) acc[q][j] = 0ULL;

    for (int ic0 = 0; ic0 < Cin; ic0 += 8) {
        // stage input rows (zero-padded halo)
        for (int idx = tid; idx < 8*3*(HW+2); idx += 256) {
            int xx  = idx % (HW+2);
            int rem = idx / (HW+2);
            int ry  = rem % 3;
            int ci  = rem / 3;
            int gy = y - 1 + ry;
            int gx = xx - 1;
            float v = 0.f;
            if (gy >= 0 && gy < HW && gx >= 0 && gx < HW)
                v = inN[(ic0 + ci) * P + gy*HW + gx];
            s_in[ci][ry][xx] = v;
        }
        // stage weights: row = ci*9+tap, col = oc (coalesced, conflict-free)
        for (int idx = tid; idx < 72*128; idx += 256) {
            int oc  = idx & 127;
            int row = idx >> 7;
            int gcol = ocBase + oc;
            float v = 0.f;
            if (gcol < Cout)
                v = wr[((long)ic0*9 + row)*Cout + gcol];
            s_w[row][oc] = v;
        }
        __syncthreads();

        for (int ci = 0; ci < 8; ci++) {
#pragma unroll
            for (int ky = 0; ky < 3; ky++) {
                u64 ivd[8];
#pragma unroll
                for (int t = 0; t < 8; t++) {
                    float v = s_in[ci][ky][tx*6 + t];
                    ivd[t] = pack2(v, v);
                }
#pragma unroll
                for (int kx = 0; kx < 3; kx++) {
                    int row = ci*9 + ky*3 + kx;
                    u64 wv[4];
#pragma unroll
                    for (int q = 0; q < 4; q++)
                        wv[q] = *(const u64*)&s_w[row][ty*8 + 2*q];
#pragma unroll
                    for (int q = 0; q < 4; q++)
#pragma unroll
                        for (int j = 0; j < 6; j++)
                            acc[q][j] = ffma2(wv[q], ivd[j+kx], acc[q][j]);
                }
            }
        }
        __syncthreads();
    }
    // epilogue
#pragma unroll
    for (int q = 0; q < 4; q++) {
        int oc0 = ocBase + ty*8 + 2*q;
#pragma unroll
        for (int j = 0; j < 6; j++) {
            float2 v = unpk(acc[q][j]);
            int px = y*HW + tx*6 + j;
            if (oc0 < Cout) {
                float r = v.x + bias[oc0];
                if (relu) r = fmaxf(r, 0.f);
                out[((long)n*Cout + oc0)*P + px] = r;
            }
            if (oc0 + 1 < Cout) {
                float r = v.y + bias[oc0+1];
                if (relu) r = fmaxf(r, 0.f);
                out[((long)n*Cout + oc0+1)*P + px] = r;
            }
        }
    }
}

// ---------------- DCN: bilinear gather into cols (b, gk, c, p) -------------------
__global__ __launch_bounds__(256) void dcn_cols_k(const float* __restrict__ cat,
                                                  const float* __restrict__ off,
                                                  float* __restrict__ cols) {
    int p  = blockIdx.x * 256 + threadIdx.x;
    int gk = blockIdx.y;
    int b  = blockIdx.z;
    int yy = p / HW, xx = p % HW;
    const float* ob = off + (long)b*189*P + p;
    float oy = ob[gk*P];
    float ox = ob[(63+gk)*P];
    float m  = ob[(126+gk)*P];
    m = 1.f / (1.f + expf(-m));
    int kk = gk % 9;
    float sy = (float)(yy - 1 + kk/3) + oy;
    float sx = (float)(xx - 1 + kk%3) + ox;
    float y0f = floorf(sy), x0f = floorf(sx);
    float wy = sy - y0f, wx = sx - x0f;
    int y0 = (int)y0f, x0 = (int)x0f;
    int y1 = y0 + 1, x1 = x0 + 1;
    bool vy0 = (y0>=0)&&(y0<HW), vy1 = (y1>=0)&&(y1<HW);
    bool vx0 = (x0>=0)&&(x0<HW), vx1 = (x1>=0)&&(x1<HW);
    int cy0 = min(max(y0,0),HW-1), cy1 = min(max(y1,0),HW-1);
    int cx0 = min(max(x0,0),HW-1), cx1 = min(max(x1,0),HW-1);
    float w00 = (vy0&&vx0) ? (1.f-wy)*(1.f-wx)*m : 0.f;
    float w01 = (vy0&&vx1) ? (1.f-wy)*wx*m       : 0.f;
    float w10 = (vy1&&vx0) ? wy*(1.f-wx)*m       : 0.f;
    float w11 = (vy1&&vx1) ? wy*wx*m             : 0.f;
    int i00 = cy0*HW+cx0, i01 = cy0*HW+cx1, i10 = cy1*HW+cx0, i11 = cy1*HW+cx1;
    int g = gk / 9;
    const float* xb = cat + (long)(b*CAT + g*64)*P;
    float* cb = cols + ((long)(b*63 + gk))*64*P + p;
#pragma unroll 4
    for (int c = 0; c < 64; c++) {
        const float* xc = xb + c*P;
        float v = w00*xc[i00] + w01*xc[i01] + w10*xc[i10] + w11*xc[i11];
        cb[c*P] = v;
    }
}

// ---------------- DCN GEMM f32x2: d[b] = W(256x4032) @ cols[b](4032x9216) --------
// fused +bias, BN, relu. grid (2, 96, 4), block 256, 128-oc tile.
// w2 layout: [k][256] (k = (g*9+kk)*64+c).
__global__ __launch_bounds__(256) void dcn_gemmf2_k(const float* __restrict__ in,
                                                    const float* __restrict__ w2,
                                                    const float* __restrict__ bias,
                                                    const float* __restrict__ gamma,
                                                    const float* __restrict__ beta,
                                                    const float* __restrict__ mean,
                                                    const float* __restrict__ var,
                                                    float* __restrict__ out) {
    __shared__ float s_in[16][HW];
    __shared__ float s_w [16][128];
    int tid = threadIdx.x;
    int tx = tid & 15, ty = tid >> 4;
    int y = blockIdx.y, b = blockIdx.z;
    int ocBase = blockIdx.x * 128;
    const float* inb = in + (long)b*4032*P + y*HW;

    u64 acc[4][6];
#pragma unroll
    for (int q=0;q<4;q++)
#pragma unroll
        for (int j=0;j<6;j++) acc[q][j] = 0ULL;

    for (int k0 = 0; k0 < 4032; k0 += 16) {
        for (int idx = tid; idx < 16*HW; idx += 256) {
            int ci = idx / HW, xx = idx % HW;
            s_in[ci][xx] = inb[(long)(k0+ci)*P + xx];
        }
        for (int idx = tid; idx < 16*128; idx += 256) {
            int ci = idx >> 7, oc = idx & 127;
            s_w[ci][oc] = w2[(long)(k0+ci)*HEAD + ocBase + oc];
        }
        __syncthreads();
#pragma unroll 2
        for (int ci = 0; ci < 16; ci++) {
            u64 ivd[6];
#pragma unroll
            for (int j = 0; j < 6; j++) {
                float v = s_in[ci][tx*6 + j];
                ivd[j] = pack2(v, v);
            }
            u64 wv[4];
#pragma unroll
            for (int q = 0; q < 4; q++)
                wv[q] = *(const u64*)&s_w[ci][ty*8 + 2*q];
#pragma unroll
            for (int q = 0; q < 4; q++)
#pragma unroll
                for (int j = 0; j < 6; j++)
                    acc[q][j] = ffma2(wv[q], ivd[j], acc[q][j]);
        }
        __syncthreads();
    }
#pragma unroll
    for (int q = 0; q < 4; q++) {
#pragma unroll
        for (int h = 0; h < 2; h++) {
            int oc = ocBase + ty*8 + 2*q + h;
            float sc = gamma[oc] * rsqrtf(var[oc] + 1e-5f);
            float bb = bias[oc] - mean[oc];
            float bt = beta[oc];
#pragma unroll
            for (int j = 0; j < 6; j++) {
                float2 v2 = unpk(acc[q][j]);
                float a = h ? v2.y : v2.x;
                float v = (a + bb) * sc + bt;
                out[((long)b*HEAD + oc)*P + y*HW + tx*6 + j] = fmaxf(v, 0.f);
            }
        }
    }
}

// ---------------- conv1x1 (Cin=256), OCT out channels per block ------------------
template<int OCT>
__global__ __launch_bounds__(256) void conv1x1_k(const float* __restrict__ in,
                                                 const float* __restrict__ w,
                                                 const float* __restrict__ bias,
                                                 float* __restrict__ out,
                                                 int Cout, int owh_mode) {
    const int Cin = 256;
    __shared__ float s_w[OCT*Cin];
    int tid = threadIdx.x;
    int n = blockIdx.y;
    int ocBase = blockIdx.z * OCT;
    for (int idx = tid; idx < OCT*Cin; idx += 256)
        s_w[idx] = w[(long)(ocBase + idx / Cin)*Cin + (idx % Cin)];
    __syncthreads();
    int px = blockIdx.x * 512 + tid * 2;
    const float* inp = in + (long)n*Cin*P + px;
    float2 acc[OCT];
#pragma unroll
    for (int o=0;o<OCT;o++) acc[o] = make_float2(0.f, 0.f);
#pragma unroll 4
    for (int ic = 0; ic < Cin; ic++) {
        float2 v = *(const float2*)(inp + (long)ic*P);
#pragma unroll
        for (int o=0;o<OCT;o++) {
            float wv = s_w[o*Cin + ic];
            acc[o].x += wv * v.x;
            acc[o].y += wv * v.y;
        }
    }
#pragma unroll
    for (int o=0;o<OCT;o++) {
        int oc = ocBase + o;
        float bv = bias[oc];
        float2 r = make_float2(acc[o].x + bv, acc[o].y + bv);
        long oidx;
        if (owh_mode) { int b = n & 3, k = n >> 2; oidx = (long)(b*14 + k*2 + oc)*P + px; }
        else          { oidx = ((long)n*Cout + oc)*P + px; }
        *(float2*)(out + oidx) = r;
    }
}

// -------------------------------- launch -----------------------------------------
extern "C" void kernel_launch(void* const* d_in, const int* in_sizes, int n_in,
                              void* d_out, int out_size) {
    const float* feat    = (const float*)d_in[0];
    const float* hm_w1   = (const float*)d_in[1];
    const float* hm_b1   = (const float*)d_in[2];
    const float* hm_w2   = (const float*)d_in[3];
    const float* hm_b2   = (const float*)d_in[4];
    const float* wh_w1   = (const float*)d_in[5];
    const float* wh_b1   = (const float*)d_in[6];
    const float* wh_w2   = (const float*)d_in[7];
    const float* wh_b2   = (const float*)d_in[8];
    const float* id_w1   = (const float*)d_in[9];
    const float* id_b1   = (const float*)d_in[10];
    const float* id_w2   = (const float*)d_in[11];
    const float* id_b2   = (const float*)d_in[12];
    const float* off_w   = (const float*)d_in[13];
    const float* off_b   = (const float*)d_in[14];
    const float* dcn_w   = (const float*)d_in[15];
    const float* dcn_b   = (const float*)d_in[16];
    const float* bn_g    = (const float*)d_in[17];
    const float* bn_b    = (const float*)d_in[18];
    const float* bn_m    = (const float*)d_in[19];
    const float* bn_v    = (const float*)d_in[20];
    const float* bz_w    = (const float*)d_in[21];
    const float* bz_b    = (const float*)d_in[22];
    float* out = (float*)d_out;

    void *p_cat, *p_wh1, *p_hm1, *p_id1, *p_off, *p_cols, *p_d;
    void *p_wr_hm, *p_wr_wh, *p_wr_id, *p_wr_off, *p_wre2;
    cudaGetSymbolAddress(&p_cat,   g_cat);
    cudaGetSymbolAddress(&p_wh1,   g_wh1);
    cudaGetSymbolAddress(&p_hm1,   g_hm1);
    cudaGetSymbolAddress(&p_id1,   g_id1);
    cudaGetSymbolAddress(&p_off,   g_off);
    cudaGetSymbolAddress(&p_cols,  g_cols);
    cudaGetSymbolAddress(&p_d,     g_d);
    cudaGetSymbolAddress(&p_wr_hm, g_wr_hm);
    cudaGetSymbolAddress(&p_wr_wh, g_wr_wh);
    cudaGetSymbolAddress(&p_wr_id, g_wr_id);
    cudaGetSymbolAddress(&p_wr_off,g_wr_off);
    cudaGetSymbolAddress(&p_wre2,  g_wre2);
    float* cat  = (float*)p_cat;
    float* wh1  = (float*)p_wh1;
    float* hm1  = (float*)p_hm1;
    float* id1  = (float*)p_id1;
    float* offv = (float*)p_off;
    float* cols = (float*)p_cols;
    float* dv   = (float*)p_d;
    float* wr_hm  = (float*)p_wr_hm;
    float* wr_wh  = (float*)p_wr_wh;
    float* wr_id  = (float*)p_wr_id;
    float* wr_off = (float*)p_wr_off;
    float* wre2   = (float*)p_wre2;

    // cat = features transposed to (B, K*C, H, W)
    build_cat_k<<<(BB*CAT*P)/256, 256>>>(feat, cat);

    // weight reorders (tiny)
    reorder_conv_w_k<<<(CC*9*HEAD + 255)/256, 256>>>(hm_w1, wr_hm, CC, HEAD);
    reorder_conv_w_k<<<(CC*9*HEAD + 255)/256, 256>>>(wh_w1, wr_wh, CC, HEAD);
    reorder_conv_w_k<<<(CAT*9*HEAD + 255)/256, 256>>>(id_w1, wr_id, CAT, HEAD);
    reorder_conv_w_k<<<(CAT*9*189 + 255)/256, 256>>>(off_w, wr_off, CAT, 189);
    reorder_dcn_w_k<<<(4032*HEAD)/256, 256>>>(dcn_w, wre2);

    // conv3x3 branches (f32x2 packed)
    conv3x3f2_k<<<dim3(2, HW, 28), 256>>>(feat, wr_wh, wh_b1, wh1, CC, HEAD, 1);
    conv3x3f2_k<<<dim3(2, HW, 4),  256>>>(feat + 3*BB*CC*P, wr_hm, hm_b1, hm1, CC, HEAD, 1);
    conv3x3f2_k<<<dim3(2, HW, 4),  256>>>(cat, wr_id, id_b1, id1, CAT, HEAD, 1);
    conv3x3f2_k<<<dim3(2, HW, 4),  256>>>(cat, wr_off, off_b, offv, CAT, 189, 0);

    // DCN
    dcn_cols_k<<<dim3(P/256, 63, BB), 256>>>(cat, offv, cols);
    dcn_gemmf2_k<<<dim3(2, HW, BB), 256>>>(cols, wre2, dcn_b, bn_g, bn_b, bn_m, bn_v, dv);

    // 1x1 heads -> output regions (hm, bz, idout, owh)
    float* out_hm  = out;
    float* out_bz  = out + (long)BB*24*P;
    float* out_id  = out_bz + (long)BB*16*P;
    float* out_owh = out_id + (long)BB*128*P;

    conv1x1_k<24><<<dim3(18, BB, 1), 256>>>(hm1, hm_w2, hm_b2, out_hm, 24, 0);
    conv1x1_k<16><<<dim3(18, BB, 1), 256>>>(dv,  bz_w,  bz_b,  out_bz, 16, 0);
    conv1x1_k<32><<<dim3(18, BB, 4), 256>>>(id1, id_w2, id_b2, out_id, 128, 0);
    conv1x1_k<2> <<<dim3(18, 28, 1), 256>>>(wh1, wh_w2, wh_b2, out_owh, 2, 1);
}

// round 6
// speedup vs baseline: 1.8428x; 1.5089x over previous
#include <cuda_runtime.h>
#include <math.h>

#define HW 96
#define P  (96*96)          // 9216
#define BB 4
#define CC 64
#define CAT 448
#define HEAD 256

typedef unsigned long long u64;

// ---------------- f32x2 packed helpers -------------------------------------------
__device__ __forceinline__ u64 pack2(float a, float b) {
    u64 r;
    asm("mov.b64 %0, {%1, %2};" : "=l"(r)
        : "r"(__float_as_uint(a)), "r"(__float_as_uint(b)));
    return r;
}
__device__ __forceinline__ u64 ffma2(u64 a, u64 b, u64 c) {
    u64 d;
    asm("fma.rn.f32x2 %0, %1, %2, %3;" : "=l"(d) : "l"(a), "l"(b), "l"(c));
    return d;
}
__device__ __forceinline__ float2 unpk(u64 v) {
    unsigned lo, hi;
    asm("mov.b64 {%0, %1}, %2;" : "=r"(lo), "=r"(hi) : "l"(v));
    return make_float2(__uint_as_float(lo), __uint_as_float(hi));
}

// ---------------- cp.async helpers -----------------------------------------------
__device__ __forceinline__ unsigned smem_u32(const void* p) {
    return (unsigned)__cvta_generic_to_shared(p);
}
__device__ __forceinline__ void cp4(unsigned dst, const float* src, bool valid) {
    int sz = valid ? 4 : 0;
    asm volatile("cp.async.ca.shared.global [%0], [%1], 4, %2;"
                 :: "r"(dst), "l"(src), "r"(sz));
}
__device__ __forceinline__ void cp16(unsigned dst, const float* src) {
    asm volatile("cp.async.cg.shared.global [%0], [%1], 16;"
                 :: "r"(dst), "l"(src));
}
__device__ __forceinline__ void cp_commit() {
    asm volatile("cp.async.commit_group;");
}
template<int N>
__device__ __forceinline__ void cp_wait() {
    asm volatile("cp.async.wait_group %0;" :: "n"(N));
}

// ---------------- scratch (device globals; no allocation allowed) ----------------
__device__ float g_cat [BB*CAT*P];
__device__ float g_wh1 [28*HEAD*P];
__device__ float g_hm1 [BB*HEAD*P];
__device__ float g_id1 [BB*HEAD*P];
__device__ float g_off [BB*189*P];
__device__ float g_cols[BB*4032*P];
__device__ float g_d   [BB*HEAD*P];
__device__ float g_wr_hm [CC*9*HEAD];
__device__ float g_wr_wh [CC*9*HEAD];
__device__ float g_wr_id [CAT*9*HEAD];
__device__ float g_wr_off[CAT*9*192];     // padded tail pad (reads beyond 189 stay in-buffer)
__device__ float g_wre2  [4032*HEAD];

// ---------------- build cat: (B, K*C, H, W) from features (K,B,C,H,W) ------------
__global__ __launch_bounds__(256) void build_cat_k(const float* __restrict__ feat,
                                                   float* __restrict__ cat) {
    int idx = blockIdx.x * 256 + threadIdx.x;
    int p  = idx % P;
    int t  = idx / P;
    int kc = t % CAT;
    int b  = t / CAT;
    int k  = kc >> 6, c = kc & 63;
    cat[idx] = feat[(((k*BB)+b)*CC + c)*P + p];
}

// ---------------- conv weight reorder: w[oc][c][tap] -> wr[(c*9+tap)][oc] --------
__global__ __launch_bounds__(256) void reorder_conv_w_k(const float* __restrict__ w,
                                                        float* __restrict__ wr,
                                                        int Cin, int Cout) {
    int idx = blockIdx.x * 256 + threadIdx.x;
    int total = Cin * 9 * Cout;
    if (idx >= total) return;
    int oc = idx % Cout;
    int r  = idx / Cout;
    int tap = r % 9, c = r / 9;
    wr[idx] = w[((long)oc*Cin + c)*9 + tap];
}

// ---------------- DCN weight reorder: -> wre2[(g*9+kk)*64+c][oc] -----------------
__global__ __launch_bounds__(256) void reorder_dcn_w_k(const float* __restrict__ dcn_w,
                                                       float* __restrict__ wre2) {
    int idx = blockIdx.x * 256 + threadIdx.x;
    int oc = idx % HEAD;
    int t  = idx / HEAD;
    int g  = t / 576;
    int r  = t % 576;
    int kk = r / 64;
    int c  = r % 64;
    wre2[idx] = dcn_w[((long)oc*CAT + g*64 + c)*9 + kk];
}

// ---------------- conv3x3 pad1, f32x2 + cp.async double-buffer -------------------
// OCT out-channels per block, THREADS = 2*OCT.  8 oc x 6 px per thread.
// grid (ocTiles, 96, nImages). Cin % 4 == 0. wr layout [(c*9+tap)][Cout].
template<int OCT, int THREADS>
__global__ __launch_bounds__(THREADS) void conv3x3f2_k(const float* __restrict__ in,
                                                       const float* __restrict__ wr,
                                                       const float* __restrict__ bias,
                                                       float* __restrict__ out,
                                                       int Cin, int Cout, int ocBase0,
                                                       int relu) {
    const int ICC = 4;
    const int INSZ = ICC*3*98;           // 1176
    const int WSZ  = ICC*9*OCT;          // 36*OCT
    __shared__ __align__(16) float s_in[2][INSZ];
    __shared__ __align__(16) float s_w [2][WSZ];
    int tid = threadIdx.x;
    int tx = tid & 15;        // px base tx*6
    int ty = tid >> 4;        // oc base ty*8
    int y  = blockIdx.y;
    int n  = blockIdx.z;
    int ocBase = ocBase0 + blockIdx.x * OCT;
    const float* inN = in + (long)n * Cin * P;
    bool w_vec4 = ((Cout & 3) == 0);

    u64 acc[4][6];
#pragma unroll
    for (int q=0;q<4;q++)
#pragma unroll
        for (int j=0;j<6;j++) acc[q][j] = 0ULL;

    auto stage = [&](int ic0, int buf) {
        unsigned sb = smem_u32(&s_in[buf][0]);
        for (int idx = tid; idx < INSZ; idx += THREADS) {
            int xx  = idx % 98;
            int rem = idx / 98;
            int ry  = rem % 3;
            int ci  = rem / 3;
            int gy = y - 1 + ry;
            int gx = xx - 1;
            bool v = (gy >= 0) && (gy < HW) && (gx >= 0) && (gx < HW);
            const float* src = inN + (long)(ic0 + ci)*P + (v ? gy*HW + gx : 0);
            cp4(sb + idx*4, src, v);
        }
        unsigned wb = smem_u32(&s_w[buf][0]);
        const float* wsrc = wr + (long)ic0*9*Cout + ocBase;
        if (w_vec4) {
            for (int idx = tid; idx < WSZ/4; idx += THREADS) {
                int row = idx / (OCT/4);
                int c4  = idx % (OCT/4);
                cp16(wb + (row*OCT + c4*4)*4, wsrc + (long)row*Cout + c4*4);
            }
        } else {
            for (int idx = tid; idx < WSZ; idx += THREADS) {
                int row = idx / OCT;
                int c   = idx % OCT;
                cp4(wb + idx*4, wsrc + (long)row*Cout + c, true);
            }
        }
    };

    int nCh = Cin / ICC;
    stage(0, 0);
    cp_commit();
    for (int c = 0; c < nCh; c++) {
        int buf = c & 1;
        if (c + 1 < nCh) { stage(c+1 == nCh ? 0 : (c+1)*ICC, buf^1); cp_commit(); cp_wait<1>(); }
        else             { cp_wait<0>(); }
        __syncthreads();
        const float* si = s_in[buf];
        const float* sw = s_w[buf];
#pragma unroll
        for (int ci = 0; ci < ICC; ci++) {
#pragma unroll
            for (int ky = 0; ky < 3; ky++) {
                u64 ivd[8];
#pragma unroll
                for (int t = 0; t < 8; t++) {
                    float v = si[(ci*3 + ky)*98 + tx*6 + t];
                    ivd[t] = pack2(v, v);
                }
#pragma unroll
                for (int kx = 0; kx < 3; kx++) {
                    int row = ci*9 + ky*3 + kx;
                    u64 wv[4];
#pragma unroll
                    for (int q = 0; q < 4; q++)
                        wv[q] = *(const u64*)&sw[row*OCT + ty*8 + 2*q];
#pragma unroll
                    for (int q = 0; q < 4; q++)
#pragma unroll
                        for (int j = 0; j < 6; j++)
                            acc[q][j] = ffma2(wv[q], ivd[j+kx], acc[q][j]);
                }
            }
        }
        __syncthreads();
    }
#pragma unroll
    for (int q = 0; q < 4; q++) {
        int oc0 = ocBase + ty*8 + 2*q;
#pragma unroll
        for (int j = 0; j < 6; j++) {
            float2 v = unpk(acc[q][j]);
            int px = y*HW + tx*6 + j;
            if (oc0 < Cout) {
                float r = v.x + bias[oc0];
                if (relu) r = fmaxf(r, 0.f);
                out[((long)n*Cout + oc0)*P + px] = r;
            }
            if (oc0 + 1 < Cout) {
                float r = v.y + bias[oc0+1];
                if (relu) r = fmaxf(r, 0.f);
                out[((long)n*Cout + oc0+1)*P + px] = r;
            }
        }
    }
}

// ---------------- DCN: bilinear gather into cols (b, gk, c, p) -------------------
__global__ __launch_bounds__(256) void dcn_cols_k(const float* __restrict__ cat,
                                                  const float* __restrict__ off,
                                                  float* __restrict__ cols) {
    int p  = blockIdx.x * 256 + threadIdx.x;
    int gk = blockIdx.y;
    int b  = blockIdx.z;
    int yy = p / HW, xx = p % HW;
    const float* ob = off + (long)b*189*P + p;
    float oy = ob[gk*P];
    float ox = ob[(63+gk)*P];
    float m  = ob[(126+gk)*P];
    m = 1.f / (1.f + expf(-m));
    int kk = gk % 9;
    float sy = (float)(yy - 1 + kk/3) + oy;
    float sx = (float)(xx - 1 + kk%3) + ox;
    float y0f = floorf(sy), x0f = floorf(sx);
    float wy = sy - y0f, wx = sx - x0f;
    int y0 = (int)y0f, x0 = (int)x0f;
    int y1 = y0 + 1, x1 = x0 + 1;
    bool vy0 = (y0>=0)&&(y0<HW), vy1 = (y1>=0)&&(y1<HW);
    bool vx0 = (x0>=0)&&(x0<HW), vx1 = (x1>=0)&&(x1<HW);
    int cy0 = min(max(y0,0),HW-1), cy1 = min(max(y1,0),HW-1);
    int cx0 = min(max(x0,0),HW-1), cx1 = min(max(x1,0),HW-1);
    float w00 = (vy0&&vx0) ? (1.f-wy)*(1.f-wx)*m : 0.f;
    float w01 = (vy0&&vx1) ? (1.f-wy)*wx*m       : 0.f;
    float w10 = (vy1&&vx0) ? wy*(1.f-wx)*m       : 0.f;
    float w11 = (vy1&&vx1) ? wy*wx*m             : 0.f;
    int i00 = cy0*HW+cx0, i01 = cy0*HW+cx1, i10 = cy1*HW+cx0, i11 = cy1*HW+cx1;
    int g = gk / 9;
    const float* xb = cat + (long)(b*CAT + g*64)*P;
    float* cb = cols + ((long)(b*63 + gk))*64*P + p;
#pragma unroll 4
    for (int c = 0; c < 64; c++) {
        const float* xc = xb + c*P;
        float v = w00*xc[i00] + w01*xc[i01] + w10*xc[i10] + w11*xc[i11];
        cb[c*P] = v;
    }
}

// ---------------- DCN GEMM f32x2 + cp.async double-buffer ------------------------
// d[b] = W(256x4032) @ cols[b](4032x9216), fused +bias, BN, relu.
// grid (2, 96, 4), block 256, 128-oc tile.  w2 layout [k][256].
__global__ __launch_bounds__(256) void dcn_gemmf2_k(const float* __restrict__ in,
                                                    const float* __restrict__ w2,
                                                    const float* __restrict__ bias,
                                                    const float* __restrict__ gamma,
                                                    const float* __restrict__ beta,
                                                    const float* __restrict__ mean,
                                                    const float* __restrict__ var,
                                                    float* __restrict__ out) {
    __shared__ __align__(16) float s_in[2][16*HW];
    __shared__ __align__(16) float s_w [2][16*128];
    int tid = threadIdx.x;
    int tx = tid & 15, ty = tid >> 4;
    int y = blockIdx.y, b = blockIdx.z;
    int ocBase = blockIdx.x * 128;
    const float* inb = in + (long)b*4032*P + y*HW;

    u64 acc[4][6];
#pragma unroll
    for (int q=0;q<4;q++)
#pragma unroll
        for (int j=0;j<6;j++) acc[q][j] = 0ULL;

    auto stage = [&](int k0, int buf) {
        unsigned sb = smem_u32(&s_in[buf][0]);
        // 16 rows x 96 floats = 384 float4
        for (int idx = tid; idx < 16*(HW/4); idx += 256) {
            int ci = idx / (HW/4);
            int x4 = idx % (HW/4);
            cp16(sb + (ci*HW + x4*4)*4, inb + (long)(k0+ci)*P + x4*4);
        }
        unsigned wb = smem_u32(&s_w[buf][0]);
        // 16 rows x 128 floats = 512 float4
        for (int idx = tid; idx < 16*32; idx += 256) {
            int ci = idx / 32;
            int c4 = idx % 32;
            cp16(wb + (ci*128 + c4*4)*4, w2 + (long)(k0+ci)*HEAD + ocBase + c4*4);
        }
    };

    const int NCH = 4032/16;   // 252
    stage(0, 0);
    cp_commit();
    for (int c = 0; c < NCH; c++) {
        int buf = c & 1;
        if (c + 1 < NCH) { stage((c+1)*16, buf^1); cp_commit(); cp_wait<1>(); }
        else             { cp_wait<0>(); }
        __syncthreads();
        const float* si = s_in[buf];
        const float* sw = s_w[buf];
#pragma unroll 4
        for (int ci = 0; ci < 16; ci++) {
            u64 ivd[6];
#pragma unroll
            for (int j = 0; j < 6; j++) {
                float v = si[ci*HW + tx*6 + j];
                ivd[j] = pack2(v, v);
            }
            u64 wv[4];
#pragma unroll
            for (int q = 0; q < 4; q++)
                wv[q] = *(const u64*)&sw[ci*128 + ty*8 + 2*q];
#pragma unroll
            for (int q = 0; q < 4; q++)
#pragma unroll
                for (int j = 0; j < 6; j++)
                    acc[q][j] = ffma2(wv[q], ivd[j], acc[q][j]);
        }
        __syncthreads();
    }
#pragma unroll
    for (int q = 0; q < 4; q++) {
#pragma unroll
        for (int h = 0; h < 2; h++) {
            int oc = ocBase + ty*8 + 2*q + h;
            float sc = gamma[oc] * rsqrtf(var[oc] + 1e-5f);
            float bb = bias[oc] - mean[oc];
            float bt = beta[oc];
#pragma unroll
            for (int j = 0; j < 6; j++) {
                float2 v2 = unpk(acc[q][j]);
                float a = h ? v2.y : v2.x;
                float v = (a + bb) * sc + bt;
                out[((long)b*HEAD + oc)*P + y*HW + tx*6 + j] = fmaxf(v, 0.f);
            }
        }
    }
}

// ---------------- conv1x1 (Cin=256), OCT out channels per block ------------------
template<int OCT>
__global__ __launch_bounds__(256) void conv1x1_k(const float* __restrict__ in,
                                                 const float* __restrict__ w,
                                                 const float* __restrict__ bias,
                                                 float* __restrict__ out,
                                                 int Cout, int owh_mode) {
    const int Cin = 256;
    __shared__ float s_w[OCT*Cin];
    int tid = threadIdx.x;
    int n = blockIdx.y;
    int ocBase = blockIdx.z * OCT;
    for (int idx = tid; idx < OCT*Cin; idx += 256)
        s_w[idx] = w[(long)(ocBase + idx / Cin)*Cin + (idx % Cin)];
    __syncthreads();
    int px = blockIdx.x * 512 + tid * 2;
    const float* inp = in + (long)n*Cin*P + px;
    float2 acc[OCT];
#pragma unroll
    for (int o=0;o<OCT;o++) acc[o] = make_float2(0.f, 0.f);
#pragma unroll 4
    for (int ic = 0; ic < Cin; ic++) {
        float2 v = *(const float2*)(inp + (long)ic*P);
#pragma unroll
        for (int o=0;o<OCT;o++) {
            float wv = s_w[o*Cin + ic];
            acc[o].x += wv * v.x;
            acc[o].y += wv * v.y;
        }
    }
#pragma unroll
    for (int o=0;o<OCT;o++) {
        int oc = ocBase + o;
        float bv = bias[oc];
        float2 r = make_float2(acc[o].x + bv, acc[o].y + bv);
        long oidx;
        if (owh_mode) { int b = n & 3, k = n >> 2; oidx = (long)(b*14 + k*2 + oc)*P + px; }
        else          { oidx = ((long)n*Cout + oc)*P + px; }
        *(float2*)(out + oidx) = r;
    }
}

// -------------------------------- launch -----------------------------------------
extern "C" void kernel_launch(void* const* d_in, const int* in_sizes, int n_in,
                              void* d_out, int out_size) {
    const float* feat    = (const float*)d_in[0];
    const float* hm_w1   = (const float*)d_in[1];
    const float* hm_b1   = (const float*)d_in[2];
    const float* hm_w2   = (const float*)d_in[3];
    const float* hm_b2   = (const float*)d_in[4];
    const float* wh_w1   = (const float*)d_in[5];
    const float* wh_b1   = (const float*)d_in[6];
    const float* wh_w2   = (const float*)d_in[7];
    const float* wh_b2   = (const float*)d_in[8];
    const float* id_w1   = (const float*)d_in[9];
    const float* id_b1   = (const float*)d_in[10];
    const float* id_w2   = (const float*)d_in[11];
    const float* id_b2   = (const float*)d_in[12];
    const float* off_w   = (const float*)d_in[13];
    const float* off_b   = (const float*)d_in[14];
    const float* dcn_w   = (const float*)d_in[15];
    const float* dcn_b   = (const float*)d_in[16];
    const float* bn_g    = (const float*)d_in[17];
    const float* bn_b    = (const float*)d_in[18];
    const float* bn_m    = (const float*)d_in[19];
    const float* bn_v    = (const float*)d_in[20];
    const float* bz_w    = (const float*)d_in[21];
    const float* bz_b    = (const float*)d_in[22];
    float* out = (float*)d_out;

    void *p_cat, *p_wh1, *p_hm1, *p_id1, *p_off, *p_cols, *p_d;
    void *p_wr_hm, *p_wr_wh, *p_wr_id, *p_wr_off, *p_wre2;
    cudaGetSymbolAddress(&p_cat,   g_cat);
    cudaGetSymbolAddress(&p_wh1,   g_wh1);
    cudaGetSymbolAddress(&p_hm1,   g_hm1);
    cudaGetSymbolAddress(&p_id1,   g_id1);
    cudaGetSymbolAddress(&p_off,   g_off);
    cudaGetSymbolAddress(&p_cols,  g_cols);
    cudaGetSymbolAddress(&p_d,     g_d);
    cudaGetSymbolAddress(&p_wr_hm, g_wr_hm);
    cudaGetSymbolAddress(&p_wr_wh, g_wr_wh);
    cudaGetSymbolAddress(&p_wr_id, g_wr_id);
    cudaGetSymbolAddress(&p_wr_off,g_wr_off);
    cudaGetSymbolAddress(&p_wre2,  g_wre2);
    float* cat  = (float*)p_cat;
    float* wh1  = (float*)p_wh1;
    float* hm1  = (float*)p_hm1;
    float* id1  = (float*)p_id1;
    float* offv = (float*)p_off;
    float* cols = (float*)p_cols;
    float* dv   = (float*)p_d;
    float* wr_hm  = (float*)p_wr_hm;
    float* wr_wh  = (float*)p_wr_wh;
    float* wr_id  = (float*)p_wr_id;
    float* wr_off = (float*)p_wr_off;
    float* wre2   = (float*)p_wre2;

    // launches 1-5: weight reorders (tiny) — placed first so launch #6 (profiled
    // by ncu -s 5 -c 1) is the wh conv, the kernel we need data on.
    reorder_conv_w_k<<<(CC*9*HEAD + 255)/256, 256>>>(hm_w1, wr_hm, CC, HEAD);
    reorder_conv_w_k<<<(CC*9*HEAD + 255)/256, 256>>>(wh_w1, wr_wh, CC, HEAD);
    reorder_conv_w_k<<<(CAT*9*HEAD + 255)/256, 256>>>(id_w1, wr_id, CAT, HEAD);
    reorder_conv_w_k<<<(CAT*9*189 + 255)/256, 256>>>(off_w, wr_off, CAT, 189);
    reorder_dcn_w_k<<<(4032*HEAD)/256, 256>>>(dcn_w, wre2);

    // launch 6: wh conv (profiled)
    conv3x3f2_k<128,256><<<dim3(2, HW, 28), 256>>>(feat, wr_wh, wh_b1, wh1, CC, HEAD, 0, 1);

    // cat = features transposed to (B, K*C, H, W)
    build_cat_k<<<(BB*CAT*P)/256, 256>>>(feat, cat);

    conv3x3f2_k<128,256><<<dim3(2, HW, 4), 256>>>(feat + 3*BB*CC*P, wr_hm, hm_b1, hm1, CC, HEAD, 0, 1);
    conv3x3f2_k<128,256><<<dim3(2, HW, 4), 256>>>(cat, wr_id, id_b1, id1, CAT, HEAD, 0, 1);
    // off conv: 128-oc main tile + 64-oc tail (covers 128..191 >= 189)
    conv3x3f2_k<128,256><<<dim3(1, HW, 4), 256>>>(cat, wr_off, off_b, offv, CAT, 189, 0, 0);
    conv3x3f2_k<64,128> <<<dim3(1, HW, 4), 128>>>(cat, wr_off, off_b, offv, CAT, 189, 128, 0);

    // DCN
    dcn_cols_k<<<dim3(P/256, 63, BB), 256>>>(cat, offv, cols);
    dcn_gemmf2_k<<<dim3(2, HW, BB), 256>>>(cols, wre2, dcn_b, bn_g, bn_b, bn_m, bn_v, dv);

    // 1x1 heads -> output regions (hm, bz, idout, owh)
    float* out_hm  = out;
    float* out_bz  = out + (long)BB*24*P;
    float* out_id  = out_bz + (long)BB*16*P;
    float* out_owh = out_id + (long)BB*128*P;

    conv1x1_k<24><<<dim3(18, BB, 1), 256>>>(hm1, hm_w2, hm_b2, out_hm, 24, 0);
    conv1x1_k<16><<<dim3(18, BB, 1), 256>>>(dv,  bz_w,  bz_b,  out_bz, 16, 0);
    conv1x1_k<32><<<dim3(18, BB, 4), 256>>>(id1, id_w2, id_b2, out_id, 128, 0);
    conv1x1_k<2> <<<dim3(18, 28, 1), 256>>>(wh1, wh_w2, wh_b2, out_owh, 2, 1);
}

// round 8
// speedup vs baseline: 1.9297x; 1.0472x over previous
#include <cuda_runtime.h>
#include <math.h>
#include <stdint.h>

#define HW 96
#define P  (96*96)          // 9216
#define BB 4
#define CC 64
#define CAT 448
#define HEAD 256

typedef unsigned long long u64;

// ---------------- f32x2 packed helpers -------------------------------------------
__device__ __forceinline__ u64 pack2(float a, float b) {
    u64 r;
    asm("mov.b64 %0, {%1, %2};" : "=l"(r)
        : "r"(__float_as_uint(a)), "r"(__float_as_uint(b)));
    return r;
}
__device__ __forceinline__ u64 ffma2(u64 a, u64 b, u64 c) {
    u64 d;
    asm("fma.rn.f32x2 %0, %1, %2, %3;" : "=l"(d) : "l"(a), "l"(b), "l"(c));
    return d;
}
__device__ __forceinline__ float2 unpk(u64 v) {
    unsigned lo, hi;
    asm("mov.b64 {%0, %1}, %2;" : "=r"(lo), "=r"(hi) : "l"(v));
    return make_float2(__uint_as_float(lo), __uint_as_float(hi));
}

// ---------------- cp.async helpers -----------------------------------------------
__device__ __forceinline__ unsigned smem_u32(const void* p) {
    return (unsigned)__cvta_generic_to_shared(p);
}
__device__ __forceinline__ void cp4(unsigned dst, const float* src, bool valid) {
    int sz = valid ? 4 : 0;
    asm volatile("cp.async.ca.shared.global [%0], [%1], 4, %2;"
                 :: "r"(dst), "l"(src), "r"(sz));
}
__device__ __forceinline__ void cp16(unsigned dst, const float* src) {
    asm volatile("cp.async.cg.shared.global [%0], [%1], 16;"
                 :: "r"(dst), "l"(src));
}
__device__ __forceinline__ void cp_commit() {
    asm volatile("cp.async.commit_group;");
}
template<int N>
__device__ __forceinline__ void cp_wait() {
    asm volatile("cp.async.wait_group %0;" :: "n"(N));
}

// ---------------- mma.sync tf32 helpers (base-target PTX, works on sm_103) -------
__device__ __forceinline__ void split_tf32(float v, unsigned &h, unsigned &l) {
    unsigned hv = __float_as_uint(v) & 0xFFFFE000u;
    h = hv;
    l = __float_as_uint(v - __uint_as_float(hv));
}
__device__ __forceinline__ void mma8(float d[4], const unsigned a[4], const unsigned b[2]) {
    asm volatile(
        "mma.sync.aligned.m16n8k8.row.col.f32.tf32.tf32.f32 "
        "{%0,%1,%2,%3}, {%4,%5,%6,%7}, {%8,%9}, {%0,%1,%2,%3};"
        : "+f"(d[0]), "+f"(d[1]), "+f"(d[2]), "+f"(d[3])
        : "r"(a[0]), "r"(a[1]), "r"(a[2]), "r"(a[3]), "r"(b[0]), "r"(b[1]));
}

// ---------------- scratch (device globals; no allocation allowed) ----------------
__device__ float g_cat [BB*CAT*P];
__device__ float g_wh1 [28*HEAD*P];
__device__ float g_hm1 [BB*HEAD*P];
__device__ float g_id1 [BB*HEAD*P];
__device__ float g_off [BB*189*P];
__device__ float g_cols[BB*4032*P];          // transposed: [b][p][k]
__device__ float g_d   [BB*HEAD*P];
__device__ float g_wr_hm [CC*9*HEAD];
__device__ float g_wr_wh [CC*9*HEAD];
__device__ float g_wr_id [CAT*9*HEAD];
__device__ float g_wr_off[CAT*9*192];
__device__ float g_wt    [HEAD*4032];        // dcn weights [oc][k]

// ---------------- build cat ------------------------------------------------------
__global__ __launch_bounds__(256) void build_cat_k(const float* __restrict__ feat,
                                                   float* __restrict__ cat) {
    int idx = blockIdx.x * 256 + threadIdx.x;
    int p  = idx % P;
    int t  = idx / P;
    int kc = t % CAT;
    int b  = t / CAT;
    int k  = kc >> 6, c = kc & 63;
    cat[idx] = feat[(((k*BB)+b)*CC + c)*P + p];
}

// ---------------- conv weight reorder: w[oc][c][tap] -> wr[(c*9+tap)][oc] --------
__global__ __launch_bounds__(256) void reorder_conv_w_k(const float* __restrict__ w,
                                                        float* __restrict__ wr,
                                                        int Cin, int Cout) {
    int idx = blockIdx.x * 256 + threadIdx.x;
    int total = Cin * 9 * Cout;
    if (idx >= total) return;
    int oc = idx % Cout;
    int r  = idx / Cout;
    int tap = r % 9, c = r / 9;
    wr[idx] = w[((long)oc*Cin + c)*9 + tap];
}

// ---------------- DCN weight reorder: -> wt[oc][(g*9+kk)*64+c] -------------------
__global__ __launch_bounds__(256) void reorder_dcn_w_k(const float* __restrict__ dcn_w,
                                                       float* __restrict__ wt) {
    int idx = blockIdx.x * 256 + threadIdx.x;   // 256*4032 exact
    int oc = idx / 4032;
    int k  = idx % 4032;
    int g  = k / 576;
    int r  = k % 576;
    int kk = r / 64;
    int c  = r % 64;
    wt[idx] = dcn_w[((long)oc*CAT + g*64 + c)*9 + kk];
}

// ---------------- conv3x3 pad1, f32x2 + cp.async double-buffer -------------------
template<int OCT, int THREADS>
__global__ __launch_bounds__(THREADS) void conv3x3f2_k(const float* __restrict__ in,
                                                       const float* __restrict__ wr,
                                                       const float* __restrict__ bias,
                                                       float* __restrict__ out,
                                                       int Cin, int Cout, int ocBase0,
                                                       int relu) {
    const int ICC = 4;
    const int INSZ = ICC*3*98;
    const int WSZ  = ICC*9*OCT;
    __shared__ __align__(16) float s_in[2][INSZ];
    __shared__ __align__(16) float s_w [2][WSZ];
    int tid = threadIdx.x;
    int tx = tid & 15;
    int ty = tid >> 4;
    int y  = blockIdx.y;
    int n  = blockIdx.z;
    int ocBase = ocBase0 + blockIdx.x * OCT;
    const float* inN = in + (long)n * Cin * P;
    bool w_vec4 = ((Cout & 3) == 0);

    u64 acc[4][6];
#pragma unroll
    for (int q=0;q<4;q++)
#pragma unroll
        for (int j=0;j<6;j++) acc[q][j] = 0ULL;

    auto stage = [&](int ic0, int buf) {
        unsigned sb = smem_u32(&s_in[buf][0]);
        for (int idx = tid; idx < INSZ; idx += THREADS) {
            int xx  = idx % 98;
            int rem = idx / 98;
            int ry  = rem % 3;
            int ci  = rem / 3;
            int gy = y - 1 + ry;
            int gx = xx - 1;
            bool v = (gy >= 0) && (gy < HW) && (gx >= 0) && (gx < HW);
            const float* src = inN + (long)(ic0 + ci)*P + (v ? gy*HW + gx : 0);
            cp4(sb + idx*4, src, v);
        }
        unsigned wb = smem_u32(&s_w[buf][0]);
        const float* wsrc = wr + (long)ic0*9*Cout + ocBase;
        if (w_vec4) {
            for (int idx = tid; idx < WSZ/4; idx += THREADS) {
                int row = idx / (OCT/4);
                int c4  = idx % (OCT/4);
                cp16(wb + (row*OCT + c4*4)*4, wsrc + (long)row*Cout + c4*4);
            }
        } else {
            for (int idx = tid; idx < WSZ; idx += THREADS) {
                int row = idx / OCT;
                int c   = idx % OCT;
                cp4(wb + idx*4, wsrc + (long)row*Cout + c, true);
            }
        }
    };

    int nCh = Cin / ICC;
    stage(0, 0);
    cp_commit();
    for (int c = 0; c < nCh; c++) {
        int buf = c & 1;
        if (c + 1 < nCh) { stage((c+1)*ICC, buf^1); cp_commit(); cp_wait<1>(); }
        else             { cp_wait<0>(); }
        __syncthreads();
        const float* si = s_in[buf];
        const float* sw = s_w[buf];
#pragma unroll
        for (int ci = 0; ci < ICC; ci++) {
#pragma unroll
            for (int ky = 0; ky < 3; ky++) {
                u64 ivd[8];
#pragma unroll
                for (int t = 0; t < 8; t++) {
                    float v = si[(ci*3 + ky)*98 + tx*6 + t];
                    ivd[t] = pack2(v, v);
                }
#pragma unroll
                for (int kx = 0; kx < 3; kx++) {
                    int row = ci*9 + ky*3 + kx;
                    u64 wv[4];
#pragma unroll
                    for (int q = 0; q < 4; q++)
                        wv[q] = *(const u64*)&sw[row*OCT + ty*8 + 2*q];
#pragma unroll
                    for (int q = 0; q < 4; q++)
#pragma unroll
                        for (int j = 0; j < 6; j++)
                            acc[q][j] = ffma2(wv[q], ivd[j+kx], acc[q][j]);
                }
            }
        }
        __syncthreads();
    }
#pragma unroll
    for (int q = 0; q < 4; q++) {
        int oc0 = ocBase + ty*8 + 2*q;
#pragma unroll
        for (int j = 0; j < 6; j++) {
            float2 v = unpk(acc[q][j]);
            int px = y*HW + tx*6 + j;
            if (oc0 < Cout) {
                float r = v.x + bias[oc0];
                if (relu) r = fmaxf(r, 0.f);
                out[((long)n*Cout + oc0)*P + px] = r;
            }
            if (oc0 + 1 < Cout) {
                float r = v.y + bias[oc0+1];
                if (relu) r = fmaxf(r, 0.f);
                out[((long)n*Cout + oc0+1)*P + px] = r;
            }
        }
    }
}

// ---------------- DCN: bilinear gather -> cols_t[b][p][k] (k contiguous) ---------
__global__ __launch_bounds__(256) void dcn_cols_k(const float* __restrict__ cat,
                                                  const float* __restrict__ off,
                                                  float* __restrict__ colsT) {
    int p  = blockIdx.x * 256 + threadIdx.x;
    int gk = blockIdx.y;
    int b  = blockIdx.z;
    int yy = p / HW, xx = p % HW;
    const float* ob = off + (long)b*189*P + p;
    float oy = ob[gk*P];
    float ox = ob[(63+gk)*P];
    float m  = ob[(126+gk)*P];
    m = 1.f / (1.f + expf(-m));
    int kk = gk % 9;
    float sy = (float)(yy - 1 + kk/3) + oy;
    float sx = (float)(xx - 1 + kk%3) + ox;
    float y0f = floorf(sy), x0f = floorf(sx);
    float wy = sy - y0f, wx = sx - x0f;
    int y0 = (int)y0f, x0 = (int)x0f;
    int y1 = y0 + 1, x1 = x0 + 1;
    bool vy0 = (y0>=0)&&(y0<HW), vy1 = (y1>=0)&&(y1<HW);
    bool vx0 = (x0>=0)&&(x0<HW), vx1 = (x1>=0)&&(x1<HW);
    int cy0 = min(max(y0,0),HW-1), cy1 = min(max(y1,0),HW-1);
    int cx0 = min(max(x0,0),HW-1), cx1 = min(max(x1,0),HW-1);
    float w00 = (vy0&&vx0) ? (1.f-wy)*(1.f-wx)*m : 0.f;
    float w01 = (vy0&&vx1) ? (1.f-wy)*wx*m       : 0.f;
    float w10 = (vy1&&vx0) ? wy*(1.f-wx)*m       : 0.f;
    float w11 = (vy1&&vx1) ? wy*wx*m             : 0.f;
    int i00 = cy0*HW+cx0, i01 = cy0*HW+cx1, i10 = cy1*HW+cx0, i11 = cy1*HW+cx1;
    int g = gk / 9;
    const float* xb = cat + (long)(b*CAT + g*64)*P;
    float* cb = colsT + ((long)b*P + p)*4032 + gk*64;
#pragma unroll 2
    for (int c4 = 0; c4 < 16; c4++) {
        const float* x0p = xb + (c4*4+0)*P;
        const float* x1p = xb + (c4*4+1)*P;
        const float* x2p = xb + (c4*4+2)*P;
        const float* x3p = xb + (c4*4+3)*P;
        float4 r;
        r.x = w00*x0p[i00] + w01*x0p[i01] + w10*x0p[i10] + w11*x0p[i11];
        r.y = w00*x1p[i00] + w01*x1p[i01] + w10*x1p[i10] + w11*x1p[i11];
        r.z = w00*x2p[i00] + w01*x2p[i01] + w10*x2p[i10] + w11*x2p[i11];
        r.w = w00*x3p[i00] + w01*x3p[i01] + w10*x3p[i10] + w11*x3p[i11];
        *(float4*)(cb + c4*4) = r;
    }
}

// ---------------- DCN GEMM via mma.sync tf32 (3xTF32) ----------------------------
// D[b][oc][p] = sum_k wt[oc][k] * colsT[b][p][k];  fused +bias, BN, relu.
// block 256 = 8 warps (4M x 2N); block tile M=128 oc, N=64 px, K=32.
// warp tile 32x32 = 2 Mtiles(16) x 4 Ntiles(8).
#define DG_PAD 36
#define DG_ASZ (128*DG_PAD)
#define DG_BSZ (64*DG_PAD)
#define DG_SMEM ((2*DG_ASZ + 2*DG_BSZ)*4)

__global__ __launch_bounds__(256) void dcn_mma_gemm_k(const float* __restrict__ colsT,
                                                      const float* __restrict__ wt,
                                                      const float* __restrict__ bias,
                                                      const float* __restrict__ gamma,
                                                      const float* __restrict__ beta,
                                                      const float* __restrict__ mean,
                                                      const float* __restrict__ var,
                                                      float* __restrict__ out) {
    extern __shared__ __align__(16) float dsm[];
    float* sA = dsm;                 // 2 x 128 x 36
    float* sB = dsm + 2*DG_ASZ;      // 2 x 64 x 36
    int tid = threadIdx.x, wid = tid >> 5, lane = tid & 31;
    int g = lane >> 2, t = lane & 3;
    int warpM = wid >> 1, warpN = wid & 1;
    int pBase  = blockIdx.x * 64;
    int ocBase = blockIdx.y * 128;
    int b      = blockIdx.z;
    const float* aG = wt + (long)ocBase * 4032;
    const float* bG = colsT + ((long)b*P + pBase) * 4032;

    float acc[2][4][4];
#pragma unroll
    for (int mt=0;mt<2;mt++)
#pragma unroll
        for (int nt=0;nt<4;nt++)
#pragma unroll
            for (int i=0;i<4;i++) acc[mt][nt][i] = 0.f;

    auto stage = [&](int k0, int buf) {
        unsigned sa = smem_u32(sA + buf*DG_ASZ);
        for (int i = tid; i < 1024; i += 256) {          // 128 rows x 8 float4
            int m = i >> 3, k4 = i & 7;
            cp16(sa + (m*DG_PAD + k4*4)*4, aG + (long)m*4032 + k0 + k4*4);
        }
        unsigned sbm = smem_u32(sB + buf*DG_BSZ);
        for (int i = tid; i < 512; i += 256) {           // 64 rows x 8 float4
            int n = i >> 3, k4 = i & 7;
            cp16(sbm + (n*DG_PAD + k4*4)*4, bG + (long)n*4032 + k0 + k4*4);
        }
    };

    const int NCH = 4032/32;   // 126
    stage(0, 0);
    cp_commit();
    for (int c = 0; c < NCH; c++) {
        int buf = c & 1;
        if (c + 1 < NCH) { stage((c+1)*32, buf^1); cp_commit(); cp_wait<1>(); }
        else             { cp_wait<0>(); }
        __syncthreads();
        const float* A  = sA + buf*DG_ASZ + (warpM*32)*DG_PAD;
        const float* Bm = sB + buf*DG_BSZ + (warpN*32)*DG_PAD;
#pragma unroll
        for (int ks = 0; ks < 4; ks++) {
            int kb = ks*8;
            unsigned ah[2][4], al[2][4];
#pragma unroll
            for (int mt = 0; mt < 2; mt++) {
                split_tf32(A[(mt*16+g  )*DG_PAD + kb + t  ], ah[mt][0], al[mt][0]);
                split_tf32(A[(mt*16+g+8)*DG_PAD + kb + t  ], ah[mt][1], al[mt][1]);
                split_tf32(A[(mt*16+g  )*DG_PAD + kb + t+4], ah[mt][2], al[mt][2]);
                split_tf32(A[(mt*16+g+8)*DG_PAD + kb + t+4], ah[mt][3], al[mt][3]);
            }
            unsigned bh[4][2], bl[4][2];
#pragma unroll
            for (int nt = 0; nt < 4; nt++) {
                split_tf32(Bm[(nt*8+g)*DG_PAD + kb + t  ], bh[nt][0], bl[nt][0]);
                split_tf32(Bm[(nt*8+g)*DG_PAD + kb + t+4], bh[nt][1], bl[nt][1]);
            }
#pragma unroll
            for (int mt = 0; mt < 2; mt++)
#pragma unroll
                for (int nt = 0; nt < 4; nt++) {
                    mma8(acc[mt][nt], ah[mt], bh[nt]);
                    mma8(acc[mt][nt], al[mt], bh[nt]);
                    mma8(acc[mt][nt], ah[mt], bl[nt]);
                }
        }
        __syncthreads();
    }

    // epilogue: BN + relu, write fp32
#pragma unroll
    for (int mt = 0; mt < 2; mt++) {
        int ocL = ocBase + warpM*32 + mt*16 + g;
        int ocH = ocL + 8;
        float scL = gamma[ocL] * rsqrtf(var[ocL] + 1e-5f);
        float bbL = bias[ocL] - mean[ocL];
        float btL = beta[ocL];
        float scH = gamma[ocH] * rsqrtf(var[ocH] + 1e-5f);
        float bbH = bias[ocH] - mean[ocH];
        float btH = beta[ocH];
        float* oL = out + ((long)b*HEAD + ocL)*P + pBase + warpN*32;
        float* oH = out + ((long)b*HEAD + ocH)*P + pBase + warpN*32;
#pragma unroll
        for (int nt = 0; nt < 4; nt++) {
            int pc = nt*8 + 2*t;
            float2 vL;
            vL.x = fmaxf((acc[mt][nt][0] + bbL)*scL + btL, 0.f);
            vL.y = fmaxf((acc[mt][nt][1] + bbL)*scL + btL, 0.f);
            float2 vH;
            vH.x = fmaxf((acc[mt][nt][2] + bbH)*scH + btH, 0.f);
            vH.y = fmaxf((acc[mt][nt][3] + bbH)*scH + btH, 0.f);
            *(float2*)(oL + pc) = vL;
            *(float2*)(oH + pc) = vH;
        }
    }
}

// ---------------- conv1x1 (Cin=256) ----------------------------------------------
template<int OCT>
__global__ __launch_bounds__(256) void conv1x1_k(const float* __restrict__ in,
                                                 const float* __restrict__ w,
                                                 const float* __restrict__ bias,
                                                 float* __restrict__ out,
                                                 int Cout, int owh_mode) {
    const int Cin = 256;
    __shared__ float s_w[OCT*Cin];
    int tid = threadIdx.x;
    int n = blockIdx.y;
    int ocBase = blockIdx.z * OCT;
    for (int idx = tid; idx < OCT*Cin; idx += 256)
        s_w[idx] = w[(long)(ocBase + idx / Cin)*Cin + (idx % Cin)];
    __syncthreads();
    int px = blockIdx.x * 512 + tid * 2;
    const float* inp = in + (long)n*Cin*P + px;
    float2 acc[OCT];
#pragma unroll
    for (int o=0;o<OCT;o++) acc[o] = make_float2(0.f, 0.f);
#pragma unroll 4
    for (int ic = 0; ic < Cin; ic++) {
        float2 v = *(const float2*)(inp + (long)ic*P);
#pragma unroll
        for (int o=0;o<OCT;o++) {
            float wv = s_w[o*Cin + ic];
            acc[o].x += wv * v.x;
            acc[o].y += wv * v.y;
        }
    }
#pragma unroll
    for (int o=0;o<OCT;o++) {
        int oc = ocBase + o;
        float bv = bias[oc];
        float2 r = make_float2(acc[o].x + bv, acc[o].y + bv);
        long oidx;
        if (owh_mode) { int b = n & 3, k = n >> 2; oidx = (long)(b*14 + k*2 + oc)*P + px; }
        else          { oidx = ((long)n*Cout + oc)*P + px; }
        *(float2*)(out + oidx) = r;
    }
}

// -------------------------------- launch -----------------------------------------
extern "C" void kernel_launch(void* const* d_in, const int* in_sizes, int n_in,
                              void* d_out, int out_size) {
    const float* feat    = (const float*)d_in[0];
    const float* hm_w1   = (const float*)d_in[1];
    const float* hm_b1   = (const float*)d_in[2];
    const float* hm_w2   = (const float*)d_in[3];
    const float* hm_b2   = (const float*)d_in[4];
    const float* wh_w1   = (const float*)d_in[5];
    const float* wh_b1   = (const float*)d_in[6];
    const float* wh_w2   = (const float*)d_in[7];
    const float* wh_b2   = (const float*)d_in[8];
    const float* id_w1   = (const float*)d_in[9];
    const float* id_b1   = (const float*)d_in[10];
    const float* id_w2   = (const float*)d_in[11];
    const float* id_b2   = (const float*)d_in[12];
    const float* off_w   = (const float*)d_in[13];
    const float* off_b   = (const float*)d_in[14];
    const float* dcn_w   = (const float*)d_in[15];
    const float* dcn_b   = (const float*)d_in[16];
    const float* bn_g    = (const float*)d_in[17];
    const float* bn_b    = (const float*)d_in[18];
    const float* bn_m    = (const float*)d_in[19];
    const float* bn_v    = (const float*)d_in[20];
    const float* bz_w    = (const float*)d_in[21];
    const float* bz_b    = (const float*)d_in[22];
    float* out = (float*)d_out;

    void *p_cat, *p_wh1, *p_hm1, *p_id1, *p_off, *p_cols, *p_d;
    void *p_wr_hm, *p_wr_wh, *p_wr_id, *p_wr_off, *p_wt;
    cudaGetSymbolAddress(&p_cat,   g_cat);
    cudaGetSymbolAddress(&p_wh1,   g_wh1);
    cudaGetSymbolAddress(&p_hm1,   g_hm1);
    cudaGetSymbolAddress(&p_id1,   g_id1);
    cudaGetSymbolAddress(&p_off,   g_off);
    cudaGetSymbolAddress(&p_cols,  g_cols);
    cudaGetSymbolAddress(&p_d,     g_d);
    cudaGetSymbolAddress(&p_wr_hm, g_wr_hm);
    cudaGetSymbolAddress(&p_wr_wh, g_wr_wh);
    cudaGetSymbolAddress(&p_wr_id, g_wr_id);
    cudaGetSymbolAddress(&p_wr_off,g_wr_off);
    cudaGetSymbolAddress(&p_wt,    g_wt);
    float* cat  = (float*)p_cat;
    float* wh1  = (float*)p_wh1;
    float* hm1  = (float*)p_hm1;
    float* id1  = (float*)p_id1;
    float* offv = (float*)p_off;
    float* cols = (float*)p_cols;
    float* dv   = (float*)p_d;
    float* wr_hm  = (float*)p_wr_hm;
    float* wr_wh  = (float*)p_wr_wh;
    float* wr_id  = (float*)p_wr_id;
    float* wr_off = (float*)p_wr_off;
    float* wt     = (float*)p_wt;

    cudaFuncSetAttribute(dcn_mma_gemm_k,
                         cudaFuncAttributeMaxDynamicSharedMemorySize, DG_SMEM);

    // #1, #2: reorders needed by wh conv
    reorder_conv_w_k<<<(CC*9*HEAD + 255)/256, 256>>>(wh_w1, wr_wh, CC, HEAD);
    reorder_conv_w_k<<<(CC*9*HEAD + 255)/256, 256>>>(hm_w1, wr_hm, CC, HEAD);
    // #3: wh conv (hoping the profiler lands here)
    conv3x3f2_k<128,256><<<dim3(2, HW, 28), 256>>>(feat, wr_wh, wh_b1, wh1, CC, HEAD, 0, 1);
    // #4: build cat
    build_cat_k<<<(BB*CAT*P)/256, 256>>>(feat, cat);
    // remaining reorders
    reorder_conv_w_k<<<(CAT*9*HEAD + 255)/256, 256>>>(id_w1, wr_id, CAT, HEAD);
    reorder_conv_w_k<<<(CAT*9*189 + 255)/256, 256>>>(off_w, wr_off, CAT, 189);
    reorder_dcn_w_k<<<(4032*HEAD)/256, 256>>>(dcn_w, wt);

    conv3x3f2_k<128,256><<<dim3(2, HW, 4), 256>>>(feat + 3*BB*CC*P, wr_hm, hm_b1, hm1, CC, HEAD, 0, 1);
    conv3x3f2_k<128,256><<<dim3(2, HW, 4), 256>>>(cat, wr_id, id_b1, id1, CAT, HEAD, 0, 1);
    conv3x3f2_k<128,256><<<dim3(1, HW, 4), 256>>>(cat, wr_off, off_b, offv, CAT, 189, 0, 0);
    conv3x3f2_k<64,128> <<<dim3(1, HW, 4), 128>>>(cat, wr_off, off_b, offv, CAT, 189, 128, 0);

    // DCN: gather (transposed cols) + mma.sync tf32 GEMM
    dcn_cols_k<<<dim3(P/256, 63, BB), 256>>>(cat, offv, cols);
    dcn_mma_gemm_k<<<dim3(P/64, 2, BB), 256, DG_SMEM>>>(cols, wt, dcn_b, bn_g, bn_b, bn_m, bn_v, dv);

    // 1x1 heads -> output regions (hm, bz, idout, owh)
    float* out_hm  = out;
    float* out_bz  = out + (long)BB*24*P;
    float* out_id  = out_bz + (long)BB*16*P;
    float* out_owh = out_id + (long)BB*128*P;

    conv1x1_k<24><<<dim3(18, BB, 1), 256>>>(hm1, hm_w2, hm_b2, out_hm, 24, 0);
    conv1x1_k<16><<<dim3(18, BB, 1), 256>>>(dv,  bz_w,  bz_b,  out_bz, 16, 0);
    conv1x1_k<32><<<dim3(18, BB, 4), 256>>>(id1, id_w2, id_b2, out_id, 128, 0);
    conv1x1_k<2> <<<dim3(18, 28, 1), 256>>>(wh1, wh_w2, wh_b2, out_owh, 2, 1);
}

// round 10
// speedup vs baseline: 2.1703x; 1.1247x over previous
#include <cuda_runtime.h>
#include <math.h>
#include <stdint.h>

#define HW 96
#define P  (96*96)          // 9216
#define BB 4
#define CC 64
#define CAT 448
#define HEAD 256

typedef unsigned long long u64;

// ---------------- cp.async helpers -----------------------------------------------
__device__ __forceinline__ unsigned smem_u32(const void* p) {
    return (unsigned)__cvta_generic_to_shared(p);
}
__device__ __forceinline__ void cp16(unsigned dst, const float* src) {
    asm volatile("cp.async.cg.shared.global [%0], [%1], 16;"
                 :: "r"(dst), "l"(src));
}
__device__ __forceinline__ void cp_commit() {
    asm volatile("cp.async.commit_group;");
}
template<int N>
__device__ __forceinline__ void cp_wait() {
    asm volatile("cp.async.wait_group %0;" :: "n"(N));
}

// ---------------- mma.sync tf32 helpers (base-target PTX) ------------------------
__device__ __forceinline__ void split_tf32(float v, unsigned &h, unsigned &l) {
    unsigned hv = __float_as_uint(v) & 0xFFFFE000u;
    h = hv;
    l = __float_as_uint(v - __uint_as_float(hv));
}
__device__ __forceinline__ void mma8(float d[4], const unsigned a[4], const unsigned b[2]) {
    asm volatile(
        "mma.sync.aligned.m16n8k8.row.col.f32.tf32.tf32.f32 "
        "{%0,%1,%2,%3}, {%4,%5,%6,%7}, {%8,%9}, {%0,%1,%2,%3};"
        : "+f"(d[0]), "+f"(d[1]), "+f"(d[2]), "+f"(d[3])
        : "r"(a[0]), "r"(a[1]), "r"(a[2]), "r"(a[3]), "r"(b[0]), "r"(b[1]));
}

// ---------------- scratch (device globals) ---------------------------------------
__device__ float g_featT[28*P*CC];          // NHWC features [n=k*4+b][p][c]
__device__ float g_colsF[28L*P*576];        // im2col(feat)  [n][p][tap*64+c]
__device__ float g_colsC[4L*P*4032];        // im2col(cat)   [b][p][tap*448+kc]
__device__ float g_cols [4L*P*4032];        // dcn gather    [b][p][gk*64+c]
__device__ float g_wh1 [28*HEAD*P];
__device__ float g_hm1 [BB*HEAD*P];
__device__ float g_id1 [BB*HEAD*P];
__device__ float g_off [BB*189*P];
__device__ float g_d   [BB*HEAD*P];
__device__ float g_wA_wh [HEAD*576];
__device__ float g_wA_hm [HEAD*576];
__device__ float g_wA_id [HEAD*4032];
__device__ float g_wA_off[189*4032];
__device__ float g_wt    [HEAD*4032];

// ---------------- transpose: feat[n][c][p] -> featT[n][p][c] ---------------------
__global__ __launch_bounds__(256) void transpose_k(const float* __restrict__ f,
                                                   float* __restrict__ fT) {
    __shared__ float sm[64][65];
    int n = blockIdx.y, p0 = blockIdx.x * 64;
    const float* src = f + (long)n*CC*P;
    for (int i = threadIdx.x; i < 4096; i += 256) {
        int c = i >> 6, x = i & 63;
        sm[x][c] = src[(long)c*P + p0 + x];
    }
    __syncthreads();
    float* dst = fT + ((long)n*P + p0)*CC;
    for (int i = threadIdx.x; i < 4096; i += 256) {
        int x = i >> 6, c = i & 63;
        dst[(long)x*CC + c] = sm[x][c];
    }
}

// ---------------- weight reorder: w[oc][c][tap] -> wA[oc][tap*C+c] ---------------
__global__ __launch_bounds__(256) void reorder_w_tap_k(const float* __restrict__ w,
                                                       float* __restrict__ wA,
                                                       int C, int Cout) {
    int idx = blockIdx.x * 256 + threadIdx.x;
    int total = Cout * C * 9;
    if (idx >= total) return;
    int oc = idx / (C*9);
    int rr = idx % (C*9);
    int tap = rr / C, c = rr % C;
    wA[idx] = w[((long)oc*C + c)*9 + tap];
}

// ---------------- DCN weight reorder: -> wt[oc][(g*9+kk)*64+c] -------------------
__global__ __launch_bounds__(256) void reorder_dcn_w_k(const float* __restrict__ dcn_w,
                                                       float* __restrict__ wt) {
    int idx = blockIdx.x * 256 + threadIdx.x;   // 256*4032 exact
    int oc = idx / 4032;
    int k  = idx % 4032;
    int g  = k / 576;
    int r  = k % 576;
    int kk = r / 64;
    int c  = r % 64;
    wt[idx] = dcn_w[((long)oc*CAT + g*64 + c)*9 + kk];
}

// ---------------- im2col for feat (C=64): colsF[n][p][tap*64+c] ------------------
__global__ __launch_bounds__(256) void im2colF_k(const float* __restrict__ xT,
                                                 float* __restrict__ cols) {
    int y = blockIdx.x, tap = blockIdx.y, n = blockIdx.z;
    int ky = tap / 3, kx = tap % 3;
    int yy = y + ky - 1;
    const float* src = xT + (long)n*P*CC;
    float* dst = cols + ((long)n*P + y*HW)*576 + tap*64;
    for (int i = threadIdx.x; i < 96*16; i += 256) {
        int x = i >> 4, c4 = i & 15;
        int xx = x + kx - 1;
        float4 v = make_float4(0.f,0.f,0.f,0.f);
        if (yy >= 0 && yy < HW && xx >= 0 && xx < HW)
            v = *(const float4*)(src + (long)(yy*HW + xx)*CC + c4*4);
        *(float4*)(dst + (long)x*576 + c4*4) = v;
    }
}

// ---------------- im2col for cat (448 ch from featT): colsC[b][p][tap*448+kc] ----
__global__ __launch_bounds__(256) void im2colC_k(const float* __restrict__ fT,
                                                 float* __restrict__ cols) {
    int y = blockIdx.x, tap = blockIdx.y, b = blockIdx.z;
    int ky = tap / 3, kx = tap % 3;
    int yy = y + ky - 1;
    float* dst = cols + ((long)b*P + y*HW)*4032 + tap*448;
    for (int i = threadIdx.x; i < 96*112; i += 256) {
        int x = i / 112, c4 = i % 112;
        int k = c4 >> 4, cc = c4 & 15;
        int xx = x + kx - 1;
        float4 v = make_float4(0.f,0.f,0.f,0.f);
        if (yy >= 0 && yy < HW && xx >= 0 && xx < HW)
            v = *(const float4*)(fT + ((long)(k*BB + b)*P + yy*HW + xx)*CC + cc*4);
        *(float4*)(dst + (long)x*4032 + c4*4) = v;
    }
}

// ---------------- DCN bilinear gather from featT -> cols[b][p][gk*64+c] ----------
__global__ __launch_bounds__(256) void dcn_cols_k(const float* __restrict__ fT,
                                                  const float* __restrict__ off,
                                                  float* __restrict__ colsT) {
    int p  = blockIdx.x * 256 + threadIdx.x;
    int gk = blockIdx.y;
    int b  = blockIdx.z;
    int yy = p / HW, xx = p % HW;
    const float* ob = off + (long)b*189*P + p;
    float oy = ob[gk*P];
    float ox = ob[(63+gk)*P];
    float m  = ob[(126+gk)*P];
    m = 1.f / (1.f + expf(-m));
    int kk = gk % 9;
    float sy = (float)(yy - 1 + kk/3) + oy;
    float sx = (float)(xx - 1 + kk%3) + ox;
    float y0f = floorf(sy), x0f = floorf(sx);
    float wy = sy - y0f, wx = sx - x0f;
    int y0 = (int)y0f, x0 = (int)x0f;
    int y1 = y0 + 1, x1 = x0 + 1;
    bool vy0 = (y0>=0)&&(y0<HW), vy1 = (y1>=0)&&(y1<HW);
    bool vx0 = (x0>=0)&&(x0<HW), vx1 = (x1>=0)&&(x1<HW);
    int cy0 = min(max(y0,0),HW-1), cy1 = min(max(y1,0),HW-1);
    int cx0 = min(max(x0,0),HW-1), cx1 = min(max(x1,0),HW-1);
    float w00 = (vy0&&vx0) ? (1.f-wy)*(1.f-wx)*m : 0.f;
    float w01 = (vy0&&vx1) ? (1.f-wy)*wx*m       : 0.f;
    float w10 = (vy1&&vx0) ? wy*(1.f-wx)*m       : 0.f;
    float w11 = (vy1&&vx1) ? wy*wx*m             : 0.f;
    int g = gk / 9;
    const float* xb = fT + (long)(g*BB + b)*P*CC;
    const float* r00 = xb + (long)(cy0*HW+cx0)*CC;
    const float* r01 = xb + (long)(cy0*HW+cx1)*CC;
    const float* r10 = xb + (long)(cy1*HW+cx0)*CC;
    const float* r11 = xb + (long)(cy1*HW+cx1)*CC;
    float* cb = colsT + ((long)b*P + p)*4032 + gk*64;
#pragma unroll 4
    for (int c4 = 0; c4 < 16; c4++) {
        float4 a = *(const float4*)(r00 + c4*4);
        float4 bq= *(const float4*)(r01 + c4*4);
        float4 cq= *(const float4*)(r10 + c4*4);
        float4 dq= *(const float4*)(r11 + c4*4);
        float4 r;
        r.x = w00*a.x + w01*bq.x + w10*cq.x + w11*dq.x;
        r.y = w00*a.y + w01*bq.y + w10*cq.y + w11*dq.y;
        r.z = w00*a.z + w01*bq.z + w10*cq.z + w11*dq.z;
        r.w = w00*a.w + w01*bq.w + w10*cq.w + w11*dq.w;
        *(float4*)(cb + c4*4) = r;
    }
}

// ---------------- generic tensor-core GEMM (3xTF32) ------------------------------
// out[n][oc][p] = sum_k A[oc][k] * B[n][p][k];  M-tile 256, N-tile 64, K-chunk 32.
// 8 warps = 4M x 2N, warp tile 64x32.  Optional BN (bn=1) and relu.
#define GM_PAD 36
#define GM_ASZ (256*GM_PAD)
#define GM_BSZ (64*GM_PAD)
#define GM_SMEM ((2*GM_ASZ + 2*GM_BSZ)*4)

__global__ __launch_bounds__(256) void gemm_tc_k(
    const float* __restrict__ A, const float* __restrict__ Bbase,
    long bStride, long oStride, int K, int Mtot,
    const float* __restrict__ bias,
    const float* __restrict__ gamma, const float* __restrict__ beta,
    const float* __restrict__ mean, const float* __restrict__ var,
    int bn, int relu, float* __restrict__ out)
{
    extern __shared__ __align__(16) float gsm[];
    float* sA = gsm;
    float* sB = gsm + 2*GM_ASZ;
    int tid = threadIdx.x, wid = tid >> 5, lane = tid & 31;
    int g = lane >> 2, t = lane & 3;
    int warpM = wid >> 1, warpN = wid & 1;
    int pBase = blockIdx.x * 64;
    int n = blockIdx.z;
    const float* Bg = Bbase + (long)n*bStride + (long)pBase*K;

    float acc[4][4][4];
#pragma unroll
    for (int mt=0;mt<4;mt++)
#pragma unroll
        for (int nt=0;nt<4;nt++)
#pragma unroll
            for (int i=0;i<4;i++) acc[mt][nt][i] = 0.f;

    auto stage = [&](int k0, int buf) {
        unsigned sa = smem_u32(sA + buf*GM_ASZ);
        for (int i = tid; i < 2048; i += 256) {
            int m = i >> 3, k4 = i & 7;
            int mm = min(m, Mtot-1);
            cp16(sa + (m*GM_PAD + k4*4)*4, A + (long)mm*K + k0 + k4*4);
        }
        unsigned sbm = smem_u32(sB + buf*GM_BSZ);
        for (int i = tid; i < 512; i += 256) {
            int r = i >> 3, k4 = i & 7;
            cp16(sbm + (r*GM_PAD + k4*4)*4, Bg + (long)r*K + k0 + k4*4);
        }
    };

    int NCH = K / 32;
    stage(0, 0);
    cp_commit();
    for (int c = 0; c < NCH; c++) {
        int buf = c & 1;
        if (c + 1 < NCH) { stage((c+1)*32, buf^1); cp_commit(); cp_wait<1>(); }
        else             { cp_wait<0>(); }
        __syncthreads();
        const float* Aw = sA + buf*GM_ASZ + (warpM*64)*GM_PAD;
        const float* Bw = sB + buf*GM_BSZ + (warpN*32)*GM_PAD;
#pragma unroll
        for (int ks = 0; ks < 4; ks++) {
            int kb = ks*8;
            unsigned ah[4][4], al[4][4];
#pragma unroll
            for (int mt = 0; mt < 4; mt++) {
                split_tf32(Aw[(mt*16+g  )*GM_PAD + kb + t  ], ah[mt][0], al[mt][0]);
                split_tf32(Aw[(mt*16+g+8)*GM_PAD + kb + t  ], ah[mt][1], al[mt][1]);
                split_tf32(Aw[(mt*16+g  )*GM_PAD + kb + t+4], ah[mt][2], al[mt][2]);
                split_tf32(Aw[(mt*16+g+8)*GM_PAD + kb + t+4], ah[mt][3], al[mt][3]);
            }
            unsigned bh[4][2], bl[4][2];
#pragma unroll
            for (int nt = 0; nt < 4; nt++) {
                split_tf32(Bw[(nt*8+g)*GM_PAD + kb + t  ], bh[nt][0], bl[nt][0]);
                split_tf32(Bw[(nt*8+g)*GM_PAD + kb + t+4], bh[nt][1], bl[nt][1]);
            }
#pragma unroll
            for (int mt = 0; mt < 4; mt++)
#pragma unroll
                for (int nt = 0; nt < 4; nt++) {
                    mma8(acc[mt][nt], ah[mt], bh[nt]);
                    mma8(acc[mt][nt], al[mt], bh[nt]);
                    mma8(acc[mt][nt], ah[mt], bl[nt]);
                }
        }
        __syncthreads();
    }

    // epilogue
#pragma unroll
    for (int mt = 0; mt < 4; mt++) {
        int ocL = warpM*64 + mt*16 + g;
        int ocH = ocL + 8;
        float scL = 1.f, bbL = 0.f, btL = 0.f;
        float scH = 1.f, bbH = 0.f, btH = 0.f;
        if (ocL < Mtot) {
            bbL = bias[ocL];
            if (bn) { scL = gamma[ocL]*rsqrtf(var[ocL]+1e-5f); bbL -= mean[ocL]; btL = beta[ocL]; }
        }
        if (ocH < Mtot) {
            bbH = bias[ocH];
            if (bn) { scH = gamma[ocH]*rsqrtf(var[ocH]+1e-5f); bbH -= mean[ocH]; btH = beta[ocH]; }
        }
        float* oL = out + (long)n*oStride + (long)ocL*P + pBase + warpN*32;
        float* oH = out + (long)n*oStride + (long)ocH*P + pBase + warpN*32;
#pragma unroll
        for (int nt = 0; nt < 4; nt++) {
            int pc = nt*8 + 2*t;
            float2 vL, vH;
            vL.x = (acc[mt][nt][0] + bbL)*scL + btL;
            vL.y = (acc[mt][nt][1] + bbL)*scL + btL;
            vH.x = (acc[mt][nt][2] + bbH)*scH + btH;
            vH.y = (acc[mt][nt][3] + bbH)*scH + btH;
            if (relu) {
                vL.x = fmaxf(vL.x, 0.f); vL.y = fmaxf(vL.y, 0.f);
                vH.x = fmaxf(vH.x, 0.f); vH.y = fmaxf(vH.y, 0.f);
            }
            if (ocL < Mtot) *(float2*)(oL + pc) = vL;
            if (ocH < Mtot) *(float2*)(oH + pc) = vH;
        }
    }
}

// ---------------- conv1x1 (Cin=256) ----------------------------------------------
template<int OCT>
__global__ __launch_bounds__(256) void conv1x1_k(const float* __restrict__ in,
                                                 const float* __restrict__ w,
                                                 const float* __restrict__ bias,
                                                 float* __restrict__ out,
                                                 int Cout, int owh_mode) {
    const int Cin = 256;
    __shared__ float s_w[OCT*Cin];
    int tid = threadIdx.x;
    int n = blockIdx.y;
    int ocBase = blockIdx.z * OCT;
    for (int idx = tid; idx < OCT*Cin; idx += 256)
        s_w[idx] = w[(long)(ocBase + idx / Cin)*Cin + (idx % Cin)];
    __syncthreads();
    int px = blockIdx.x * 512 + tid * 2;
    const float* inp = in + (long)n*Cin*P + px;
    float2 acc[OCT];
#pragma unroll
    for (int o=0;o<OCT;o++) acc[o] = make_float2(0.f, 0.f);
#pragma unroll 4
    for (int ic = 0; ic < Cin; ic++) {
        float2 v = *(const float2*)(inp + (long)ic*P);
#pragma unroll
        for (int o=0;o<OCT;o++) {
            float wv = s_w[o*Cin + ic];
            acc[o].x += wv * v.x;
            acc[o].y += wv * v.y;
        }
    }
#pragma unroll
    for (int o=0;o<OCT;o++) {
        int oc = ocBase + o;
        float bv = bias[oc];
        float2 r = make_float2(acc[o].x + bv, acc[o].y + bv);
        long oidx;
        if (owh_mode) { int b = n & 3, k = n >> 2; oidx = (long)(b*14 + k*2 + oc)*P + px; }
        else          { oidx = ((long)n*Cout + oc)*P + px; }
        *(float2*)(out + oidx) = r;
    }
}

// -------------------------------- launch -----------------------------------------
extern "C" void kernel_launch(void* const* d_in, const int* in_sizes, int n_in,
                              void* d_out, int out_size) {
    const float* feat    = (const float*)d_in[0];
    const float* hm_w1   = (const float*)d_in[1];
    const float* hm_b1   = (const float*)d_in[2];
    const float* hm_w2   = (const float*)d_in[3];
    const float* hm_b2   = (const float*)d_in[4];
    const float* wh_w1   = (const float*)d_in[5];
    const float* wh_b1   = (const float*)d_in[6];
    const float* wh_w2   = (const float*)d_in[7];
    const float* wh_b2   = (const float*)d_in[8];
    const float* id_w1   = (const float*)d_in[9];
    const float* id_b1   = (const float*)d_in[10];
    const float* id_w2   = (const float*)d_in[11];
    const float* id_b2   = (const float*)d_in[12];
    const float* off_w   = (const float*)d_in[13];
    const float* off_b   = (const float*)d_in[14];
    const float* dcn_w   = (const float*)d_in[15];
    const float* dcn_b   = (const float*)d_in[16];
    const float* bn_g    = (const float*)d_in[17];
    const float* bn_b    = (const float*)d_in[18];
    const float* bn_m    = (const float*)d_in[19];
    const float* bn_v    = (const float*)d_in[20];
    const float* bz_w    = (const float*)d_in[21];
    const float* bz_b    = (const float*)d_in[22];
    float* out = (float*)d_out;

    void *p_featT, *p_colsF, *p_colsC, *p_cols, *p_wh1, *p_hm1, *p_id1, *p_off, *p_d;
    void *p_wA_wh, *p_wA_hm, *p_wA_id, *p_wA_off, *p_wt;
    cudaGetSymbolAddress(&p_featT, g_featT);
    cudaGetSymbolAddress(&p_colsF, g_colsF);
    cudaGetSymbolAddress(&p_colsC, g_colsC);
    cudaGetSymbolAddress(&p_cols,  g_cols);
    cudaGetSymbolAddress(&p_wh1,   g_wh1);
    cudaGetSymbolAddress(&p_hm1,   g_hm1);
    cudaGetSymbolAddress(&p_id1,   g_id1);
    cudaGetSymbolAddress(&p_off,   g_off);
    cudaGetSymbolAddress(&p_d,     g_d);
    cudaGetSymbolAddress(&p_wA_wh, g_wA_wh);
    cudaGetSymbolAddress(&p_wA_hm, g_wA_hm);
    cudaGetSymbolAddress(&p_wA_id, g_wA_id);
    cudaGetSymbolAddress(&p_wA_off,g_wA_off);
    cudaGetSymbolAddress(&p_wt,    g_wt);
    float* featT = (float*)p_featT;
    float* colsF = (float*)p_colsF;
    float* colsC = (float*)p_colsC;
    float* cols  = (float*)p_cols;
    float* wh1   = (float*)p_wh1;
    float* hm1   = (float*)p_hm1;
    float* id1   = (float*)p_id1;
    float* offv  = (float*)p_off;
    float* dv    = (float*)p_d;
    float* wA_wh = (float*)p_wA_wh;
    float* wA_hm = (float*)p_wA_hm;
    float* wA_id = (float*)p_wA_id;
    float* wA_off= (float*)p_wA_off;
    float* wt    = (float*)p_wt;

    cudaFuncSetAttribute(gemm_tc_k,
                         cudaFuncAttributeMaxDynamicSharedMemorySize, GM_SMEM);

    const long bsF = (long)P*576, osH = (long)HEAD*P;
    const long bsC = (long)P*4032;

    // #1..#5 (so #6 = wh gemm gets profiled)
    transpose_k<<<dim3(144, 28), 256>>>(feat, featT);                       // 1
    reorder_w_tap_k<<<(HEAD*576+255)/256, 256>>>(wh_w1, wA_wh, CC, HEAD);   // 2
    im2colF_k<<<dim3(HW, 9, 28), 256>>>(featT, colsF);                      // 3
    reorder_w_tap_k<<<(HEAD*576+255)/256, 256>>>(hm_w1, wA_hm, CC, HEAD);   // 4
    reorder_w_tap_k<<<(HEAD*4032+255)/256, 256>>>(id_w1, wA_id, CAT, HEAD); // 5
    // #6: wh GEMM (K=576, 28 images)
    gemm_tc_k<<<dim3(144, 1, 28), 256, GM_SMEM>>>(wA_wh, colsF, bsF, osH, 576, HEAD,
        wh_b1, bn_g, bn_b, bn_m, bn_v, 0, 1, wh1);
    // hm GEMM (images 12..15 of colsF)
    gemm_tc_k<<<dim3(144, 1, 4), 256, GM_SMEM>>>(wA_hm, colsF + 12L*P*576, bsF, osH, 576, HEAD,
        hm_b1, bn_g, bn_b, bn_m, bn_v, 0, 1, hm1);

    reorder_w_tap_k<<<(189*4032+255)/256, 256>>>(off_w, wA_off, CAT, 189);
    reorder_dcn_w_k<<<(4032*HEAD)/256, 256>>>(dcn_w, wt);
    im2colC_k<<<dim3(HW, 9, BB), 256>>>(featT, colsC);

    // id GEMM (K=4032)
    gemm_tc_k<<<dim3(144, 1, BB), 256, GM_SMEM>>>(wA_id, colsC, bsC, osH, 4032, HEAD,
        id_b1, bn_g, bn_b, bn_m, bn_v, 0, 1, id1);
    // off GEMM (M=189, no relu)
    gemm_tc_k<<<dim3(144, 1, BB), 256, GM_SMEM>>>(wA_off, colsC, bsC, (long)189*P, 4032, 189,
        off_b, bn_g, bn_b, bn_m, bn_v, 0, 0, offv);

    // DCN gather + GEMM (BN + relu fused)
    dcn_cols_k<<<dim3(P/256, 63, BB), 256>>>(featT, offv, cols);
    gemm_tc_k<<<dim3(144, 1, BB), 256, GM_SMEM>>>(wt, cols, bsC, osH, 4032, HEAD,
        dcn_b, bn_g, bn_b, bn_m, bn_v, 1, 1, dv);

    // 1x1 heads -> output regions (hm, bz, idout, owh)
    float* out_hm  = out;
    float* out_bz  = out + (long)BB*24*P;
    float* out_id  = out_bz + (long)BB*16*P;
    float* out_owh = out_id + (long)BB*128*P;

    conv1x1_k<24><<<dim3(18, BB, 1), 256>>>(hm1, hm_w2, hm_b2, out_hm, 24, 0);
    conv1x1_k<16><<<dim3(18, BB, 1), 256>>>(dv,  bz_w,  bz_b,  out_bz, 16, 0);
    conv1x1_k<32><<<dim3(18, BB, 4), 256>>>(id1, id_w2, id_b2, out_id, 128, 0);
    conv1x1_k<2> <<<dim3(18, 28, 1), 256>>>(wh1, wh_w2, wh_b2, out_owh, 2, 1);
}

// round 11
// speedup vs baseline: 2.2006x; 1.0139x over previous
#include <cuda_runtime.h>
#include <math.h>
#include <stdint.h>

#define HW 96
#define P  (96*96)          // 9216
#define BB 4
#define CC 64
#define CAT 448
#define HEAD 256

// ---------------- cp.async helpers -----------------------------------------------
__device__ __forceinline__ unsigned smem_u32(const void* p) {
    return (unsigned)__cvta_generic_to_shared(p);
}
__device__ __forceinline__ void cp16(unsigned dst, const float* src) {
    asm volatile("cp.async.cg.shared.global [%0], [%1], 16;"
                 :: "r"(dst), "l"(src));
}
__device__ __forceinline__ void cp16z(unsigned dst, const float* src, int sz) {
    asm volatile("cp.async.cg.shared.global [%0], [%1], 16, %2;"
                 :: "r"(dst), "l"(src), "r"(sz));
}
__device__ __forceinline__ void cp_commit() {
    asm volatile("cp.async.commit_group;");
}
template<int N>
__device__ __forceinline__ void cp_wait() {
    asm volatile("cp.async.wait_group %0;" :: "n"(N));
}

// ---------------- mma.sync tf32 helpers (base-target PTX) ------------------------
__device__ __forceinline__ void split_tf32(float v, unsigned &h, unsigned &l) {
    unsigned hv = __float_as_uint(v) & 0xFFFFE000u;
    h = hv;
    l = __float_as_uint(v - __uint_as_float(hv));
}
__device__ __forceinline__ void mma8(float d[4], const unsigned a[4], const unsigned b[2]) {
    asm volatile(
        "mma.sync.aligned.m16n8k8.row.col.f32.tf32.tf32.f32 "
        "{%0,%1,%2,%3}, {%4,%5,%6,%7}, {%8,%9}, {%0,%1,%2,%3};"
        : "+f"(d[0]), "+f"(d[1]), "+f"(d[2]), "+f"(d[3])
        : "r"(a[0]), "r"(a[1]), "r"(a[2]), "r"(a[3]), "r"(b[0]), "r"(b[1]));
}

// ---------------- scratch (device globals) ---------------------------------------
__device__ float g_featT[28*P*CC];          // NHWC features [n=k*4+b][p][c]
__device__ float g_cols [4L*P*4032];        // dcn gather    [b][p][gk*64+c]
__device__ float g_wh1 [28*HEAD*P];
__device__ float g_hm1 [BB*HEAD*P];
__device__ float g_id1 [BB*HEAD*P];
__device__ float g_off [BB*189*P];
__device__ float g_d   [BB*HEAD*P];
__device__ float g_wA_wh [HEAD*576];
__device__ float g_wA_hm [HEAD*576];
__device__ float g_wA_id [HEAD*4032];
__device__ float g_wA_off[189*4032];
__device__ float g_wt    [HEAD*4032];

// ---------------- transpose: feat[n][c][p] -> featT[n][p][c] ---------------------
__global__ __launch_bounds__(256) void transpose_k(const float* __restrict__ f,
                                                   float* __restrict__ fT) {
    __shared__ float sm[64][65];
    int n = blockIdx.y, p0 = blockIdx.x * 64;
    const float* src = f + (long)n*CC*P;
    for (int i = threadIdx.x; i < 4096; i += 256) {
        int c = i >> 6, x = i & 63;
        sm[x][c] = src[(long)c*P + p0 + x];
    }
    __syncthreads();
    float* dst = fT + ((long)n*P + p0)*CC;
    for (int i = threadIdx.x; i < 4096; i += 256) {
        int x = i >> 6, c = i & 63;
        dst[(long)x*CC + c] = sm[x][c];
    }
}

// ---------------- weight reorder: w[oc][c][tap] -> wA[oc][tap*C+c] ---------------
__global__ __launch_bounds__(256) void reorder_w_tap_k(const float* __restrict__ w,
                                                       float* __restrict__ wA,
                                                       int C, int Cout) {
    int idx = blockIdx.x * 256 + threadIdx.x;
    int total = Cout * C * 9;
    if (idx >= total) return;
    int oc = idx / (C*9);
    int rr = idx % (C*9);
    int tap = rr / C, c = rr % C;
    wA[idx] = w[((long)oc*C + c)*9 + tap];
}

// cat-mode weight reorder: w[oc][kimg*64+c][tap] -> wA[oc][(tap*7+kimg)*64+c]
__global__ __launch_bounds__(256) void reorder_w_cat_k(const float* __restrict__ w,
                                                       float* __restrict__ wA,
                                                       int Cout) {
    int idx = blockIdx.x * 256 + threadIdx.x;
    int total = Cout * 4032;
    if (idx >= total) return;
    int oc = idx / 4032;
    int rr = idx % 4032;          // (tap*7+kimg)*64+c
    int c  = rr & 63;
    int gi = rr >> 6;
    int tap = gi / 7, kimg = gi % 7;
    wA[idx] = w[((long)oc*CAT + kimg*64 + c)*9 + tap];
}

// ---------------- DCN weight reorder: -> wt[oc][(g*9+kk)*64+c] -------------------
__global__ __launch_bounds__(256) void reorder_dcn_w_k(const float* __restrict__ dcn_w,
                                                       float* __restrict__ wt) {
    int idx = blockIdx.x * 256 + threadIdx.x;   // 256*4032 exact
    int oc = idx / 4032;
    int k  = idx % 4032;
    int g  = k / 576;
    int r  = k % 576;
    int kk = r / 64;
    int c  = r % 64;
    wt[idx] = dcn_w[((long)oc*CAT + g*64 + c)*9 + kk];
}

// ---------------- DCN bilinear gather from featT -> cols[b][p][gk*64+c] ----------
__global__ __launch_bounds__(256) void dcn_cols_k(const float* __restrict__ fT,
                                                  const float* __restrict__ off,
                                                  float* __restrict__ colsT) {
    int p  = blockIdx.x * 256 + threadIdx.x;
    int gk = blockIdx.y;
    int b  = blockIdx.z;
    int yy = p / HW, xx = p % HW;
    const float* ob = off + (long)b*189*P + p;
    float oy = ob[gk*P];
    float ox = ob[(63+gk)*P];
    float m  = ob[(126+gk)*P];
    m = 1.f / (1.f + expf(-m));
    int kk = gk % 9;
    float sy = (float)(yy - 1 + kk/3) + oy;
    float sx = (float)(xx - 1 + kk%3) + ox;
    float y0f = floorf(sy), x0f = floorf(sx);
    float wy = sy - y0f, wx = sx - x0f;
    int y0 = (int)y0f, x0 = (int)x0f;
    int y1 = y0 + 1, x1 = x0 + 1;
    bool vy0 = (y0>=0)&&(y0<HW), vy1 = (y1>=0)&&(y1<HW);
    bool vx0 = (x0>=0)&&(x0<HW), vx1 = (x1>=0)&&(x1<HW);
    int cy0 = min(max(y0,0),HW-1), cy1 = min(max(y1,0),HW-1);
    int cx0 = min(max(x0,0),HW-1), cx1 = min(max(x1,0),HW-1);
    float w00 = (vy0&&vx0) ? (1.f-wy)*(1.f-wx)*m : 0.f;
    float w01 = (vy0&&vx1) ? (1.f-wy)*wx*m       : 0.f;
    float w10 = (vy1&&vx0) ? wy*(1.f-wx)*m       : 0.f;
    float w11 = (vy1&&vx1) ? wy*wx*m             : 0.f;
    int g = gk / 9;
    const float* xb = fT + (long)(g*BB + b)*P*CC;
    const float* r00 = xb + (long)(cy0*HW+cx0)*CC;
    const float* r01 = xb + (long)(cy0*HW+cx1)*CC;
    const float* r10 = xb + (long)(cy1*HW+cx0)*CC;
    const float* r11 = xb + (long)(cy1*HW+cx1)*CC;
    float* cb = colsT + ((long)b*P + p)*4032 + gk*64;
#pragma unroll 4
    for (int c4 = 0; c4 < 16; c4++) {
        float4 a = *(const float4*)(r00 + c4*4);
        float4 bq= *(const float4*)(r01 + c4*4);
        float4 cq= *(const float4*)(r10 + c4*4);
        float4 dq= *(const float4*)(r11 + c4*4);
        float4 r;
        r.x = w00*a.x + w01*bq.x + w10*cq.x + w11*dq.x;
        r.y = w00*a.y + w01*bq.y + w10*cq.y + w11*dq.y;
        r.z = w00*a.z + w01*bq.z + w10*cq.z + w11*dq.z;
        r.w = w00*a.w + w01*bq.w + w10*cq.w + w11*dq.w;
        *(float4*)(cb + c4*4) = r;
    }
}

// ---------------- generic tensor-core GEMM (3xTF32), implicit-im2col B -----------
// out[z][oc][p] = sum_k A[oc][k] * B[z][p][k]
// mode 0: B explicit [p][K] rows at Bbase + z*zStride
// mode 1: B implicit im2col of NHWC featT (C=64), group gi=tap (K=576)
// mode 2: B implicit im2col of cat (7 images), gi=tap*7+kimg (K=4032)
#define GM_PAD 36
#define GM_ASZ (256*GM_PAD)
#define GM_BSZ (64*GM_PAD)
#define GM_SMEM ((2*GM_ASZ + 2*GM_BSZ)*4)

__global__ __launch_bounds__(256) void gemm_tc_k(
    const float* __restrict__ A, const float* __restrict__ Bbase,
    long zStride, long kStride, int mode,
    long oStride, int K, int Mtot,
    const float* __restrict__ bias,
    const float* __restrict__ gamma, const float* __restrict__ beta,
    const float* __restrict__ mean, const float* __restrict__ var,
    int bn, int relu, float* __restrict__ out)
{
    extern __shared__ __align__(16) float gsm[];
    float* sA = gsm;
    float* sB = gsm + 2*GM_ASZ;
    int tid = threadIdx.x, wid = tid >> 5, lane = tid & 31;
    int g = lane >> 2, t = lane & 3;
    int warpM = wid >> 1, warpN = wid & 1;
    int pBase = blockIdx.x * 64;
    int z = blockIdx.z;
    const float* Bz = Bbase + (long)z*zStride;

    float acc[4][4][4];
#pragma unroll
    for (int mt=0;mt<4;mt++)
#pragma unroll
        for (int nt=0;nt<4;nt++)
#pragma unroll
            for (int i=0;i<4;i++) acc[mt][nt][i] = 0.f;

    auto stage = [&](int k0, int buf) {
        unsigned sa = smem_u32(sA + buf*GM_ASZ);
        for (int i = tid; i < 2048; i += 256) {
            int m = i >> 3, k4 = i & 7;
            int mm = min(m, Mtot-1);
            cp16(sa + (m*GM_PAD + k4*4)*4, A + (long)mm*K + k0 + k4*4);
        }
        unsigned sbm = smem_u32(sB + buf*GM_BSZ);
        if (mode == 0) {
            for (int i = tid; i < 512; i += 256) {
                int r = i >> 3, k4 = i & 7;
                cp16(sbm + (r*GM_PAD + k4*4)*4, Bz + (long)(pBase + r)*K + k0 + k4*4);
            }
        } else {
            int cIdx = k0 >> 5;
            int gi = cIdx >> 1, half = cIdx & 1;
            int tap, kimg;
            if (mode == 1) { tap = gi; kimg = 0; }
            else           { tap = gi / 7; kimg = gi - tap*7; }
            int dy = tap/3 - 1, dx = tap - (tap/3)*3 - 1;
            const float* srcB = Bz + (long)kimg*kStride;
            for (int i = tid; i < 512; i += 256) {
                int r = i >> 3, k4 = i & 7;
                int p = pBase + r;
                int y = p / HW, x = p - y*HW;
                int yy = y + dy, xx = x + dx;
                bool ok = ((unsigned)yy < HW) && ((unsigned)xx < HW);
                const float* s = ok ? srcB + ((long)(yy*HW + xx))*CC + half*32 + k4*4
                                    : srcB;
                cp16z(sbm + (r*GM_PAD + k4*4)*4, s, ok ? 16 : 0);
            }
        }
    };

    int NCH = K / 32;
    stage(0, 0);
    cp_commit();
    for (int c = 0; c < NCH; c++) {
        int buf = c & 1;
        if (c + 1 < NCH) { stage((c+1)*32, buf^1); cp_commit(); cp_wait<1>(); }
        else             { cp_wait<0>(); }
        __syncthreads();
        const float* Aw = sA + buf*GM_ASZ + (warpM*64)*GM_PAD;
        const float* Bw = sB + buf*GM_BSZ + (warpN*32)*GM_PAD;
#pragma unroll
        for (int ks = 0; ks < 4; ks++) {
            int kb = ks*8;
            unsigned ah[4][4], al[4][4];
#pragma unroll
            for (int mt = 0; mt < 4; mt++) {
                split_tf32(Aw[(mt*16+g  )*GM_PAD + kb + t  ], ah[mt][0], al[mt][0]);
                split_tf32(Aw[(mt*16+g+8)*GM_PAD + kb + t  ], ah[mt][1], al[mt][1]);
                split_tf32(Aw[(mt*16+g  )*GM_PAD + kb + t+4], ah[mt][2], al[mt][2]);
                split_tf32(Aw[(mt*16+g+8)*GM_PAD + kb + t+4], ah[mt][3], al[mt][3]);
            }
            unsigned bh[4][2], bl[4][2];
#pragma unroll
            for (int nt = 0; nt < 4; nt++) {
                split_tf32(Bw[(nt*8+g)*GM_PAD + kb + t  ], bh[nt][0], bl[nt][0]);
                split_tf32(Bw[(nt*8+g)*GM_PAD + kb + t+4], bh[nt][1], bl[nt][1]);
            }
#pragma unroll
            for (int mt = 0; mt < 4; mt++)
#pragma unroll
                for (int nt = 0; nt < 4; nt++) {
                    mma8(acc[mt][nt], ah[mt], bh[nt]);
                    mma8(acc[mt][nt], al[mt], bh[nt]);
                    mma8(acc[mt][nt], ah[mt], bl[nt]);
                }
        }
        __syncthreads();
    }

    // epilogue
#pragma unroll
    for (int mt = 0; mt < 4; mt++) {
        int ocL = warpM*64 + mt*16 + g;
        int ocH = ocL + 8;
        float scL = 1.f, bbL = 0.f, btL = 0.f;
        float scH = 1.f, bbH = 0.f, btH = 0.f;
        if (ocL < Mtot) {
            bbL = bias[ocL];
            if (bn) { scL = gamma[ocL]*rsqrtf(var[ocL]+1e-5f); bbL -= mean[ocL]; btL = beta[ocL]; }
        }
        if (ocH < Mtot) {
            bbH = bias[ocH];
            if (bn) { scH = gamma[ocH]*rsqrtf(var[ocH]+1e-5f); bbH -= mean[ocH]; btH = beta[ocH]; }
        }
        float* oL = out + (long)z*oStride + (long)ocL*P + pBase + warpN*32;
        float* oH = out + (long)z*oStride + (long)ocH*P + pBase + warpN*32;
#pragma unroll
        for (int nt = 0; nt < 4; nt++) {
            int pc = nt*8 + 2*t;
            float2 vL, vH;
            vL.x = (acc[mt][nt][0] + bbL)*scL + btL;
            vL.y = (acc[mt][nt][1] + bbL)*scL + btL;
            vH.x = (acc[mt][nt][2] + bbH)*scH + btH;
            vH.y = (acc[mt][nt][3] + bbH)*scH + btH;
            if (relu) {
                vL.x = fmaxf(vL.x, 0.f); vL.y = fmaxf(vL.y, 0.f);
                vH.x = fmaxf(vH.x, 0.f); vH.y = fmaxf(vH.y, 0.f);
            }
            if (ocL < Mtot) *(float2*)(oL + pc) = vL;
            if (ocH < Mtot) *(float2*)(oH + pc) = vH;
        }
    }
}

// ---------------- conv1x1 (Cin=256) ----------------------------------------------
template<int OCT>
__global__ __launch_bounds__(256) void conv1x1_k(const float* __restrict__ in,
                                                 const float* __restrict__ w,
                                                 const float* __restrict__ bias,
                                                 float* __restrict__ out,
                                                 int Cout, int owh_mode) {
    const int Cin = 256;
    __shared__ float s_w[OCT*Cin];
    int tid = threadIdx.x;
    int n = blockIdx.y;
    int ocBase = blockIdx.z * OCT;
    for (int idx = tid; idx < OCT*Cin; idx += 256)
        s_w[idx] = w[(long)(ocBase + idx / Cin)*Cin + (idx % Cin)];
    __syncthreads();
    int px = blockIdx.x * 512 + tid * 2;
    const float* inp = in + (long)n*Cin*P + px;
    float2 acc[OCT];
#pragma unroll
    for (int o=0;o<OCT;o++) acc[o] = make_float2(0.f, 0.f);
#pragma unroll 4
    for (int ic = 0; ic < Cin; ic++) {
        float2 v = *(const float2*)(inp + (long)ic*P);
#pragma unroll
        for (int o=0;o<OCT;o++) {
            float wv = s_w[o*Cin + ic];
            acc[o].x += wv * v.x;
            acc[o].y += wv * v.y;
        }
    }
#pragma unroll
    for (int o=0;o<OCT;o++) {
        int oc = ocBase + o;
        float bv = bias[oc];
        float2 r = make_float2(acc[o].x + bv, acc[o].y + bv);
        long oidx;
        if (owh_mode) { int b = n & 3, k = n >> 2; oidx = (long)(b*14 + k*2 + oc)*P + px; }
        else          { oidx = ((long)n*Cout + oc)*P + px; }
        *(float2*)(out + oidx) = r;
    }
}

// -------------------------------- launch -----------------------------------------
extern "C" void kernel_launch(void* const* d_in, const int* in_sizes, int n_in,
                              void* d_out, int out_size) {
    const float* feat    = (const float*)d_in[0];
    const float* hm_w1   = (const float*)d_in[1];
    const float* hm_b1   = (const float*)d_in[2];
    const float* hm_w2   = (const float*)d_in[3];
    const float* hm_b2   = (const float*)d_in[4];
    const float* wh_w1   = (const float*)d_in[5];
    const float* wh_b1   = (const float*)d_in[6];
    const float* wh_w2   = (const float*)d_in[7];
    const float* wh_b2   = (const float*)d_in[8];
    const float* id_w1   = (const float*)d_in[9];
    const float* id_b1   = (const float*)d_in[10];
    const float* id_w2   = (const float*)d_in[11];
    const float* id_b2   = (const float*)d_in[12];
    const float* off_w   = (const float*)d_in[13];
    const float* off_b   = (const float*)d_in[14];
    const float* dcn_w   = (const float*)d_in[15];
    const float* dcn_b   = (const float*)d_in[16];
    const float* bn_g    = (const float*)d_in[17];
    const float* bn_b    = (const float*)d_in[18];
    const float* bn_m    = (const float*)d_in[19];
    const float* bn_v    = (const float*)d_in[20];
    const float* bz_w    = (const float*)d_in[21];
    const float* bz_b    = (const float*)d_in[22];
    float* out = (float*)d_out;

    void *p_featT, *p_cols, *p_wh1, *p_hm1, *p_id1, *p_off, *p_d;
    void *p_wA_wh, *p_wA_hm, *p_wA_id, *p_wA_off, *p_wt;
    cudaGetSymbolAddress(&p_featT, g_featT);
    cudaGetSymbolAddress(&p_cols,  g_cols);
    cudaGetSymbolAddress(&p_wh1,   g_wh1);
    cudaGetSymbolAddress(&p_hm1,   g_hm1);
    cudaGetSymbolAddress(&p_id1,   g_id1);
    cudaGetSymbolAddress(&p_off,   g_off);
    cudaGetSymbolAddress(&p_d,     g_d);
    cudaGetSymbolAddress(&p_wA_wh, g_wA_wh);
    cudaGetSymbolAddress(&p_wA_hm, g_wA_hm);
    cudaGetSymbolAddress(&p_wA_id, g_wA_id);
    cudaGetSymbolAddress(&p_wA_off,g_wA_off);
    cudaGetSymbolAddress(&p_wt,    g_wt);
    float* featT = (float*)p_featT;
    float* cols  = (float*)p_cols;
    float* wh1   = (float*)p_wh1;
    float* hm1   = (float*)p_hm1;
    float* id1   = (float*)p_id1;
    float* offv  = (float*)p_off;
    float* dv    = (float*)p_d;
    float* wA_wh = (float*)p_wA_wh;
    float* wA_hm = (float*)p_wA_hm;
    float* wA_id = (float*)p_wA_id;
    float* wA_off= (float*)p_wA_off;
    float* wt    = (float*)p_wt;

    cudaFuncSetAttribute(gemm_tc_k,
                         cudaFuncAttributeMaxDynamicSharedMemorySize, GM_SMEM);

    const long osH = (long)HEAD*P;
    const long zImg = (long)P*CC;       // per-image featT stride
    const long kImg = (long)BB*P*CC;    // per-kimg stride within cat

    // 1 transpose, 2 reorder wh, 3 reorder hm, 4 wh GEMM (profile target)
    transpose_k<<<dim3(144, 28), 256>>>(feat, featT);
    reorder_w_tap_k<<<(HEAD*576+255)/256, 256>>>(wh_w1, wA_wh, CC, HEAD);
    reorder_w_tap_k<<<(HEAD*576+255)/256, 256>>>(hm_w1, wA_hm, CC, HEAD);
    gemm_tc_k<<<dim3(144, 1, 28), 256, GM_SMEM>>>(wA_wh, featT, zImg, 0, 1, osH, 576, HEAD,
        wh_b1, bn_g, bn_b, bn_m, bn_v, 0, 1, wh1);
    // hm: images 12..15
    gemm_tc_k<<<dim3(144, 1, 4), 256, GM_SMEM>>>(wA_hm, featT + 12*zImg, zImg, 0, 1, osH, 576, HEAD,
        hm_b1, bn_g, bn_b, bn_m, bn_v, 0, 1, hm1);

    reorder_w_cat_k<<<(HEAD*4032+255)/256, 256>>>(id_w1, wA_id, HEAD);
    reorder_w_cat_k<<<(189*4032+255)/256, 256>>>(off_w, wA_off, 189);
    reorder_dcn_w_k<<<(4032*HEAD)/256, 256>>>(dcn_w, wt);

    // id / off GEMMs: cat-mode implicit im2col (z = b, kimg stride = 4 images)
    gemm_tc_k<<<dim3(144, 1, BB), 256, GM_SMEM>>>(wA_id, featT, zImg, kImg, 2, osH, 4032, HEAD,
        id_b1, bn_g, bn_b, bn_m, bn_v, 0, 1, id1);
    gemm_tc_k<<<dim3(144, 1, BB), 256, GM_SMEM>>>(wA_off, featT, zImg, kImg, 2, (long)189*P, 4032, 189,
        off_b, bn_g, bn_b, bn_m, bn_v, 0, 0, offv);

    // DCN gather + GEMM (explicit B, BN + relu fused)
    dcn_cols_k<<<dim3(P/256, 63, BB), 256>>>(featT, offv, cols);
    gemm_tc_k<<<dim3(144, 1, BB), 256, GM_SMEM>>>(wt, cols, (long)P*4032, 0, 0, osH, 4032, HEAD,
        dcn_b, bn_g, bn_b, bn_m, bn_v, 1, 1, dv);

    // 1x1 heads -> output regions (hm, bz, idout, owh)
    float* out_hm  = out;
    float* out_bz  = out + (long)BB*24*P;
    float* out_id  = out_bz + (long)BB*16*P;
    float* out_owh = out_id + (long)BB*128*P;

    conv1x1_k<24><<<dim3(18, BB, 1), 256>>>(hm1, hm_w2, hm_b2, out_hm, 24, 0);
    conv1x1_k<16><<<dim3(18, BB, 1), 256>>>(dv,  bz_w,  bz_b,  out_bz, 16, 0);
    conv1x1_k<32><<<dim3(18, BB, 4), 256>>>(id1, id_w2, id_b2, out_id, 128, 0);
    conv1x1_k<2> <<<dim3(18, 28, 1), 256>>>(wh1, wh_w2, wh_b2, out_owh, 2, 1);
}

// round 12
// speedup vs baseline: 2.6082x; 1.1853x over previous
#include <cuda_runtime.h>
#include <cuda_bf16.h>
#include <math.h>
#include <stdint.h>

#define HW 96
#define P  (96*96)          // 9216
#define BB 4
#define CC 64
#define CAT 448
#define HEAD 256

typedef __nv_bfloat16 bf16;

// ---------------- cp.async helpers -----------------------------------------------
__device__ __forceinline__ unsigned smem_u32(const void* p) {
    return (unsigned)__cvta_generic_to_shared(p);
}
__device__ __forceinline__ void cp16(unsigned dst, const void* src) {
    asm volatile("cp.async.cg.shared.global [%0], [%1], 16;"
                 :: "r"(dst), "l"(src));
}
__device__ __forceinline__ void cp16z(unsigned dst, const void* src, int sz) {
    asm volatile("cp.async.cg.shared.global [%0], [%1], 16, %2;"
                 :: "r"(dst), "l"(src), "r"(sz));
}
__device__ __forceinline__ void cp_commit() {
    asm volatile("cp.async.commit_group;");
}
template<int N>
__device__ __forceinline__ void cp_wait() {
    asm volatile("cp.async.wait_group %0;" :: "n"(N));
}

// ---------------- bf16 split helpers ---------------------------------------------
__device__ __forceinline__ void split_bf16(float v, bf16 &h, bf16 &l) {
    h = __float2bfloat16_rn(v);
    l = __float2bfloat16_rn(v - __bfloat162float(h));
}

// ---------------- mma.sync m16n8k16 bf16 -----------------------------------------
__device__ __forceinline__ void mma16(float d[4], const unsigned a[4], const unsigned b[2]) {
    asm volatile(
        "mma.sync.aligned.m16n8k16.row.col.f32.bf16.bf16.f32 "
        "{%0,%1,%2,%3}, {%4,%5,%6,%7}, {%8,%9}, {%0,%1,%2,%3};"
        : "+f"(d[0]), "+f"(d[1]), "+f"(d[2]), "+f"(d[3])
        : "r"(a[0]), "r"(a[1]), "r"(a[2]), "r"(a[3]), "r"(b[0]), "r"(b[1]));
}

// ---------------- scratch (device globals) ---------------------------------------
__device__ float g_featT[28*P*CC];          // NHWC fp32 (for DCN bilinear)
__device__ bf16  g_fTh  [28*P*CC];          // NHWC bf16 hi
__device__ bf16  g_fTl  [28*P*CC];          // NHWC bf16 lo
__device__ bf16  g_colsh[4L*P*4032];        // dcn gather hi [b][p][gk*64+c]
__device__ bf16  g_colsl[4L*P*4032];
__device__ float g_wh1 [28*HEAD*P];
__device__ float g_hm1 [BB*HEAD*P];
__device__ float g_id1 [BB*HEAD*P];
__device__ float g_off [BB*189*P];
__device__ float g_d   [BB*HEAD*P];
__device__ bf16  g_wh_h[HEAD*576],  g_wh_l[HEAD*576];
__device__ bf16  g_hm_h[HEAD*576],  g_hm_l[HEAD*576];
__device__ bf16  g_id_h[HEAD*4032], g_id_l[HEAD*4032];
__device__ bf16  g_of_h[189*4032],  g_of_l[189*4032];
__device__ bf16  g_wt_h[HEAD*4032], g_wt_l[HEAD*4032];

// ---------------- transpose + bf16 split: feat[n][c][p] -> featT/fTh/fTl ---------
__global__ __launch_bounds__(256) void transpose_k(const float* __restrict__ f,
                                                   float* __restrict__ fT,
                                                   bf16* __restrict__ fTh,
                                                   bf16* __restrict__ fTl) {
    __shared__ float sm[64][65];
    int n = blockIdx.y, p0 = blockIdx.x * 64;
    const float* src = f + (long)n*CC*P;
    for (int i = threadIdx.x; i < 4096; i += 256) {
        int c = i >> 6, x = i & 63;
        sm[x][c] = src[(long)c*P + p0 + x];
    }
    __syncthreads();
    long base = ((long)n*P + p0)*CC;
    for (int i = threadIdx.x; i < 4096; i += 256) {
        int x = i >> 6, c = i & 63;
        float v = sm[x][c];
        long o = base + (long)x*CC + c;
        fT[o] = v;
        bf16 h, l; split_bf16(v, h, l);
        fTh[o] = h; fTl[o] = l;
    }
}

// ---------------- weight reorders (fp32 -> bf16 hi/lo) ---------------------------
// tap-mode: w[oc][c][tap] -> wA[oc][tap*C+c]
__global__ __launch_bounds__(256) void reorder_w_tap_k(const float* __restrict__ w,
                                                       bf16* __restrict__ wh,
                                                       bf16* __restrict__ wl,
                                                       int C, int Cout) {
    int idx = blockIdx.x * 256 + threadIdx.x;
    int total = Cout * C * 9;
    if (idx >= total) return;
    int oc = idx / (C*9);
    int rr = idx % (C*9);
    int tap = rr / C, c = rr % C;
    float v = w[((long)oc*C + c)*9 + tap];
    bf16 h, l; split_bf16(v, h, l);
    wh[idx] = h; wl[idx] = l;
}

// cat-mode: w[oc][kimg*64+c][tap] -> wA[oc][(tap*7+kimg)*64+c]
__global__ __launch_bounds__(256) void reorder_w_cat_k(const float* __restrict__ w,
                                                       bf16* __restrict__ wh,
                                                       bf16* __restrict__ wl,
                                                       int Cout) {
    int idx = blockIdx.x * 256 + threadIdx.x;
    int total = Cout * 4032;
    if (idx >= total) return;
    int oc = idx / 4032;
    int rr = idx % 4032;
    int c  = rr & 63;
    int gi = rr >> 6;
    int tap = gi / 7, kimg = gi % 7;
    float v = w[((long)oc*CAT + kimg*64 + c)*9 + tap];
    bf16 h, l; split_bf16(v, h, l);
    wh[idx] = h; wl[idx] = l;
}

// dcn: -> wt[oc][(g*9+kk)*64+c]
__global__ __launch_bounds__(256) void reorder_dcn_w_k(const float* __restrict__ dcn_w,
                                                       bf16* __restrict__ wh,
                                                       bf16* __restrict__ wl) {
    int idx = blockIdx.x * 256 + threadIdx.x;   // 256*4032 exact
    int oc = idx / 4032;
    int k  = idx % 4032;
    int g  = k / 576;
    int r  = k % 576;
    int kk = r / 64;
    int c  = r % 64;
    float v = dcn_w[((long)oc*CAT + g*64 + c)*9 + kk];
    bf16 h, l; split_bf16(v, h, l);
    wh[idx] = h; wl[idx] = l;
}

// ---------------- DCN bilinear gather (fp32 math) -> bf16 hi/lo cols -------------
__global__ __launch_bounds__(256) void dcn_cols_k(const float* __restrict__ fT,
                                                  const float* __restrict__ off,
                                                  bf16* __restrict__ colsH,
                                                  bf16* __restrict__ colsL) {
    int p  = blockIdx.x * 256 + threadIdx.x;
    int gk = blockIdx.y;
    int b  = blockIdx.z;
    int yy = p / HW, xx = p % HW;
    const float* ob = off + (long)b*189*P + p;
    float oy = ob[gk*P];
    float ox = ob[(63+gk)*P];
    float m  = ob[(126+gk)*P];
    m = 1.f / (1.f + expf(-m));
    int kk = gk % 9;
    float sy = (float)(yy - 1 + kk/3) + oy;
    float sx = (float)(xx - 1 + kk%3) + ox;
    float y0f = floorf(sy), x0f = floorf(sx);
    float wy = sy - y0f, wx = sx - x0f;
    int y0 = (int)y0f, x0 = (int)x0f;
    int y1 = y0 + 1, x1 = x0 + 1;
    bool vy0 = (y0>=0)&&(y0<HW), vy1 = (y1>=0)&&(y1<HW);
    bool vx0 = (x0>=0)&&(x0<HW), vx1 = (x1>=0)&&(x1<HW);
    int cy0 = min(max(y0,0),HW-1), cy1 = min(max(y1,0),HW-1);
    int cx0 = min(max(x0,0),HW-1), cx1 = min(max(x1,0),HW-1);
    float w00 = (vy0&&vx0) ? (1.f-wy)*(1.f-wx)*m : 0.f;
    float w01 = (vy0&&vx1) ? (1.f-wy)*wx*m       : 0.f;
    float w10 = (vy1&&vx0) ? wy*(1.f-wx)*m       : 0.f;
    float w11 = (vy1&&vx1) ? wy*wx*m             : 0.f;
    int g = gk / 9;
    const float* xb = fT + (long)(g*BB + b)*P*CC;
    const float* r00 = xb + (long)(cy0*HW+cx0)*CC;
    const float* r01 = xb + (long)(cy0*HW+cx1)*CC;
    const float* r10 = xb + (long)(cy1*HW+cx0)*CC;
    const float* r11 = xb + (long)(cy1*HW+cx1)*CC;
    long cbo = ((long)b*P + p)*4032 + gk*64;
#pragma unroll 4
    for (int c4 = 0; c4 < 16; c4++) {
        float4 a = *(const float4*)(r00 + c4*4);
        float4 bq= *(const float4*)(r01 + c4*4);
        float4 cq= *(const float4*)(r10 + c4*4);
        float4 dq= *(const float4*)(r11 + c4*4);
        float4 r;
        r.x = w00*a.x + w01*bq.x + w10*cq.x + w11*dq.x;
        r.y = w00*a.y + w01*bq.y + w10*cq.y + w11*dq.y;
        r.z = w00*a.z + w01*bq.z + w10*cq.z + w11*dq.z;
        r.w = w00*a.w + w01*bq.w + w10*cq.w + w11*dq.w;
        bf16 hx,lx,hy,ly,hz,lz,hw,lw;
        split_bf16(r.x,hx,lx); split_bf16(r.y,hy,ly);
        split_bf16(r.z,hz,lz); split_bf16(r.w,hw,lw);
        __nv_bfloat162 h01; h01.x = hx; h01.y = hy;
        __nv_bfloat162 h23; h23.x = hz; h23.y = hw;
        __nv_bfloat162 l01; l01.x = lx; l01.y = ly;
        __nv_bfloat162 l23; l23.x = lz; l23.y = lw;
        *(__nv_bfloat162*)(colsH + cbo + c4*4    ) = h01;
        *(__nv_bfloat162*)(colsH + cbo + c4*4 + 2) = h23;
        *(__nv_bfloat162*)(colsL + cbo + c4*4    ) = l01;
        *(__nv_bfloat162*)(colsL + cbo + c4*4 + 2) = l23;
    }
}

// ---------------- generic bf16 tensor-core GEMM (3-term split) -------------------
// out[z][oc][p] = sum_k A[oc][k] * B[z][p][k]
// mode 0: B explicit bf16 [p][K] at Bh/Bl + z*zStride
// mode 1: B implicit im2col of NHWC fTh/fTl (C=64), gi=tap (K=576)
// mode 2: B implicit im2col of cat (7 images), gi=tap*7+kimg (K=4032)
#define PADB 40
#define SA_BUF (256*PADB)           // bf16 elements per A buffer
#define SB_BUF (64*PADB)
#define OFF_AH 0
#define OFF_AL (2*SA_BUF*2)
#define OFF_BH (4*SA_BUF*2)
#define OFF_BL (4*SA_BUF*2 + 2*SB_BUF*2)
#define GM_SMEM (4*SA_BUF*2 + 4*SB_BUF*2)   // 102400 bytes

__global__ __launch_bounds__(256) void gemm_tc_k(
    const bf16* __restrict__ Ah, const bf16* __restrict__ Al,
    const bf16* __restrict__ Bh, const bf16* __restrict__ Bl,
    long zStride, long kStride, int mode,
    long oStride, int K, int Mtot,
    const float* __restrict__ bias,
    const float* __restrict__ gamma, const float* __restrict__ beta,
    const float* __restrict__ mean, const float* __restrict__ var,
    int bn, int relu, float* __restrict__ out)
{
    extern __shared__ __align__(16) char gsm[];
    bf16* sAh = (bf16*)(gsm + OFF_AH);
    bf16* sAl = (bf16*)(gsm + OFF_AL);
    bf16* sBh = (bf16*)(gsm + OFF_BH);
    bf16* sBl = (bf16*)(gsm + OFF_BL);
    int tid = threadIdx.x, wid = tid >> 5, lane = tid & 31;
    int g = lane >> 2, t = lane & 3;
    int warpM = wid >> 1, warpN = wid & 1;
    int pBase = blockIdx.x * 64;
    int z = blockIdx.z;
    const bf16* Bzh = Bh + (long)z*zStride;
    const bf16* Bzl = Bl + (long)z*zStride;

    float acc[4][4][4];
#pragma unroll
    for (int mt=0;mt<4;mt++)
#pragma unroll
        for (int nt=0;nt<4;nt++)
#pragma unroll
            for (int i=0;i<4;i++) acc[mt][nt][i] = 0.f;

    auto stage = [&](int k0, int buf) {
        unsigned sah = smem_u32(sAh + buf*SA_BUF);
        unsigned sal = smem_u32(sAl + buf*SA_BUF);
        for (int i = tid; i < 1024; i += 256) {       // 256 rows x 4 x 8bf16
            int m = i >> 2, j = i & 3;
            int mm = min(m, Mtot-1);
            long so = (long)mm*K + k0 + j*8;
            unsigned d = (m*PADB + j*8)*2;
            cp16(sah + d, Ah + so);
            cp16(sal + d, Al + so);
        }
        unsigned sbh = smem_u32(sBh + buf*SB_BUF);
        unsigned sbl = smem_u32(sBl + buf*SB_BUF);
        if (mode == 0) {
            for (int i = tid; i < 256; i += 256) {    // 64 rows x 4 x 8bf16
                int r = i >> 2, j = i & 3;
                long so = (long)(pBase + r)*K + k0 + j*8;
                unsigned d = (r*PADB + j*8)*2;
                cp16(sbh + d, Bzh + so);
                cp16(sbl + d, Bzl + so);
            }
        } else {
            int cIdx = k0 >> 5;
            int gi = cIdx >> 1, half = cIdx & 1;
            int tap, kimg;
            if (mode == 1) { tap = gi; kimg = 0; }
            else           { tap = gi / 7; kimg = gi - tap*7; }
            int dy = tap/3 - 1, dx = tap - (tap/3)*3 - 1;
            const bf16* sh = Bzh + (long)kimg*kStride;
            const bf16* sl = Bzl + (long)kimg*kStride;
            for (int i = tid; i < 256; i += 256) {
                int r = i >> 2, j = i & 3;
                int p = pBase + r;
                int y = p / HW, x = p - y*HW;
                int yy = y + dy, xx = x + dx;
                bool ok = ((unsigned)yy < HW) && ((unsigned)xx < HW);
                long so = ok ? ((long)(yy*HW + xx))*CC + half*32 + j*8 : 0;
                int sz = ok ? 16 : 0;
                unsigned d = (r*PADB + j*8)*2;
                cp16z(sbh + d, sh + so, sz);
                cp16z(sbl + d, sl + so, sz);
            }
        }
    };

    int NCH = K / 32;
    stage(0, 0);
    cp_commit();
    for (int c = 0; c < NCH; c++) {
        int buf = c & 1;
        if (c + 1 < NCH) { stage((c+1)*32, buf^1); cp_commit(); cp_wait<1>(); }
        else             { cp_wait<0>(); }
        __syncthreads();
        const bf16* Awh = sAh + buf*SA_BUF + (warpM*64)*PADB;
        const bf16* Awl = sAl + buf*SA_BUF + (warpM*64)*PADB;
        const bf16* Bwh = sBh + buf*SB_BUF + (warpN*32)*PADB;
        const bf16* Bwl = sBl + buf*SB_BUF + (warpN*32)*PADB;
#pragma unroll
        for (int ks = 0; ks < 2; ks++) {
            int kb = ks*16;
            unsigned bh[4][2], bl[4][2];
#pragma unroll
            for (int nt = 0; nt < 4; nt++) {
                int ro = (nt*8 + g)*PADB + kb + 2*t;
                bh[nt][0] = *(const unsigned*)(Bwh + ro);
                bh[nt][1] = *(const unsigned*)(Bwh + ro + 8);
                bl[nt][0] = *(const unsigned*)(Bwl + ro);
                bl[nt][1] = *(const unsigned*)(Bwl + ro + 8);
            }
#pragma unroll
            for (int mt = 0; mt < 4; mt++) {
                int r0 = (mt*16 + g)*PADB + kb + 2*t;
                int r1 = (mt*16 + g + 8)*PADB + kb + 2*t;
                unsigned ah[4], al[4];
                ah[0] = *(const unsigned*)(Awh + r0);
                ah[1] = *(const unsigned*)(Awh + r1);
                ah[2] = *(const unsigned*)(Awh + r0 + 8);
                ah[3] = *(const unsigned*)(Awh + r1 + 8);
                al[0] = *(const unsigned*)(Awl + r0);
                al[1] = *(const unsigned*)(Awl + r1);
                al[2] = *(const unsigned*)(Awl + r0 + 8);
                al[3] = *(const unsigned*)(Awl + r1 + 8);
#pragma unroll
                for (int nt = 0; nt < 4; nt++) {
                    mma16(acc[mt][nt], ah, bh[nt]);
                    mma16(acc[mt][nt], al, bh[nt]);
                    mma16(acc[mt][nt], ah, bl[nt]);
                }
            }
        }
        __syncthreads();
    }

    // epilogue
#pragma unroll
    for (int mt = 0; mt < 4; mt++) {
        int ocL = warpM*64 + mt*16 + g;
        int ocH = ocL + 8;
        float scL = 1.f, bbL = 0.f, btL = 0.f;
        float scH = 1.f, bbH = 0.f, btH = 0.f;
        if (ocL < Mtot) {
            bbL = bias[ocL];
            if (bn) { scL = gamma[ocL]*rsqrtf(var[ocL]+1e-5f); bbL -= mean[ocL]; btL = beta[ocL]; }
        }
        if (ocH < Mtot) {
            bbH = bias[ocH];
            if (bn) { scH = gamma[ocH]*rsqrtf(var[ocH]+1e-5f); bbH -= mean[ocH]; btH = beta[ocH]; }
        }
        float* oL = out + (long)z*oStride + (long)ocL*P + pBase + warpN*32;
        float* oH = out + (long)z*oStride + (long)ocH*P + pBase + warpN*32;
#pragma unroll
        for (int nt = 0; nt < 4; nt++) {
            int pc = nt*8 + 2*t;
            float2 vL, vH;
            vL.x = (acc[mt][nt][0] + bbL)*scL + btL;
            vL.y = (acc[mt][nt][1] + bbL)*scL + btL;
            vH.x = (acc[mt][nt][2] + bbH)*scH + btH;
            vH.y = (acc[mt][nt][3] + bbH)*scH + btH;
            if (relu) {
                vL.x = fmaxf(vL.x, 0.f); vL.y = fmaxf(vL.y, 0.f);
                vH.x = fmaxf(vH.x, 0.f); vH.y = fmaxf(vH.y, 0.f);
            }
            if (ocL < Mtot) *(float2*)(oL + pc) = vL;
            if (ocH < Mtot) *(float2*)(oH + pc) = vH;
        }
    }
}

// ---------------- conv1x1 (Cin=256) ----------------------------------------------
template<int OCT>
__global__ __launch_bounds__(256) void conv1x1_k(const float* __restrict__ in,
                                                 const float* __restrict__ w,
                                                 const float* __restrict__ bias,
                                                 float* __restrict__ out,
                                                 int Cout, int owh_mode) {
    const int Cin = 256;
    __shared__ float s_w[OCT*Cin];
    int tid = threadIdx.x;
    int n = blockIdx.y;
    int ocBase = blockIdx.z * OCT;
    for (int idx = tid; idx < OCT*Cin; idx += 256)
        s_w[idx] = w[(long)(ocBase + idx / Cin)*Cin + (idx % Cin)];
    __syncthreads();
    int px = blockIdx.x * 512 + tid * 2;
    const float* inp = in + (long)n*Cin*P + px;
    float2 acc[OCT];
#pragma unroll
    for (int o=0;o<OCT;o++) acc[o] = make_float2(0.f, 0.f);
#pragma unroll 4
    for (int ic = 0; ic < Cin; ic++) {
        float2 v = *(const float2*)(inp + (long)ic*P);
#pragma unroll
        for (int o=0;o<OCT;o++) {
            float wv = s_w[o*Cin + ic];
            acc[o].x += wv * v.x;
            acc[o].y += wv * v.y;
        }
    }
#pragma unroll
    for (int o=0;o<OCT;o++) {
        int oc = ocBase + o;
        float bv = bias[oc];
        float2 r = make_float2(acc[o].x + bv, acc[o].y + bv);
        long oidx;
        if (owh_mode) { int b = n & 3, k = n >> 2; oidx = (long)(b*14 + k*2 + oc)*P + px; }
        else          { oidx = ((long)n*Cout + oc)*P + px; }
        *(float2*)(out + oidx) = r;
    }
}

// -------------------------------- launch -----------------------------------------
extern "C" void kernel_launch(void* const* d_in, const int* in_sizes, int n_in,
                              void* d_out, int out_size) {
    const float* feat    = (const float*)d_in[0];
    const float* hm_w1   = (const float*)d_in[1];
    const float* hm_b1   = (const float*)d_in[2];
    const float* hm_w2   = (const float*)d_in[3];
    const float* hm_b2   = (const float*)d_in[4];
    const float* wh_w1   = (const float*)d_in[5];
    const float* wh_b1   = (const float*)d_in[6];
    const float* wh_w2   = (const float*)d_in[7];
    const float* wh_b2   = (const float*)d_in[8];
    const float* id_w1   = (const float*)d_in[9];
    const float* id_b1   = (const float*)d_in[10];
    const float* id_w2   = (const float*)d_in[11];
    const float* id_b2   = (const float*)d_in[12];
    const float* off_w   = (const float*)d_in[13];
    const float* off_b   = (const float*)d_in[14];
    const float* dcn_w   = (const float*)d_in[15];
    const float* dcn_b   = (const float*)d_in[16];
    const float* bn_g    = (const float*)d_in[17];
    const float* bn_b    = (const float*)d_in[18];
    const float* bn_m    = (const float*)d_in[19];
    const float* bn_v    = (const float*)d_in[20];
    const float* bz_w    = (const float*)d_in[21];
    const float* bz_b    = (const float*)d_in[22];
    float* out = (float*)d_out;

    void *p_featT, *p_fTh, *p_fTl, *p_colsh, *p_colsl;
    void *p_wh1, *p_hm1, *p_id1, *p_off, *p_d;
    void *p_wh_h, *p_wh_l, *p_hm_h, *p_hm_l, *p_id_h, *p_id_l, *p_of_h, *p_of_l, *p_wt_h, *p_wt_l;
    cudaGetSymbolAddress(&p_featT, g_featT);
    cudaGetSymbolAddress(&p_fTh,   g_fTh);
    cudaGetSymbolAddress(&p_fTl,   g_fTl);
    cudaGetSymbolAddress(&p_colsh, g_colsh);
    cudaGetSymbolAddress(&p_colsl, g_colsl);
    cudaGetSymbolAddress(&p_wh1,   g_wh1);
    cudaGetSymbolAddress(&p_hm1,   g_hm1);
    cudaGetSymbolAddress(&p_id1,   g_id1);
    cudaGetSymbolAddress(&p_off,   g_off);
    cudaGetSymbolAddress(&p_d,     g_d);
    cudaGetSymbolAddress(&p_wh_h,  g_wh_h);
    cudaGetSymbolAddress(&p_wh_l,  g_wh_l);
    cudaGetSymbolAddress(&p_hm_h,  g_hm_h);
    cudaGetSymbolAddress(&p_hm_l,  g_hm_l);
    cudaGetSymbolAddress(&p_id_h,  g_id_h);
    cudaGetSymbolAddress(&p_id_l,  g_id_l);
    cudaGetSymbolAddress(&p_of_h,  g_of_h);
    cudaGetSymbolAddress(&p_of_l,  g_of_l);
    cudaGetSymbolAddress(&p_wt_h,  g_wt_h);
    cudaGetSymbolAddress(&p_wt_l,  g_wt_l);
    float* featT = (float*)p_featT;
    bf16*  fTh   = (bf16*)p_fTh;
    bf16*  fTl   = (bf16*)p_fTl;
    bf16*  colsh = (bf16*)p_colsh;
    bf16*  colsl = (bf16*)p_colsl;
    float* wh1   = (float*)p_wh1;
    float* hm1   = (float*)p_hm1;
    float* id1   = (float*)p_id1;
    float* offv  = (float*)p_off;
    float* dv    = (float*)p_d;

    cudaFuncSetAttribute(gemm_tc_k,
                         cudaFuncAttributeMaxDynamicSharedMemorySize, GM_SMEM);

    const long osH = (long)HEAD*P;
    const long zImg = (long)P*CC;       // per-image stride (elements)
    const long kImg = (long)BB*P*CC;    // per-kimg stride within cat

    // 1 transpose, 2 reorder wh, 3 reorder hm, 4 wh GEMM (profile target)
    transpose_k<<<dim3(144, 28), 256>>>(feat, featT, fTh, fTl);
    reorder_w_tap_k<<<(HEAD*576+255)/256, 256>>>(wh_w1, (bf16*)p_wh_h, (bf16*)p_wh_l, CC, HEAD);
    reorder_w_tap_k<<<(HEAD*576+255)/256, 256>>>(hm_w1, (bf16*)p_hm_h, (bf16*)p_hm_l, CC, HEAD);
    gemm_tc_k<<<dim3(144, 1, 28), 256, GM_SMEM>>>((bf16*)p_wh_h, (bf16*)p_wh_l, fTh, fTl,
        zImg, 0, 1, osH, 576, HEAD, wh_b1, bn_g, bn_b, bn_m, bn_v, 0, 1, wh1);
    // hm: images 12..15
    gemm_tc_k<<<dim3(144, 1, 4), 256, GM_SMEM>>>((bf16*)p_hm_h, (bf16*)p_hm_l, fTh + 12*zImg, fTl + 12*zImg,
        zImg, 0, 1, osH, 576, HEAD, hm_b1, bn_g, bn_b, bn_m, bn_v, 0, 1, hm1);

    reorder_w_cat_k<<<(HEAD*4032+255)/256, 256>>>(id_w1, (bf16*)p_id_h, (bf16*)p_id_l, HEAD);
    reorder_w_cat_k<<<(189*4032+255)/256, 256>>>(off_w, (bf16*)p_of_h, (bf16*)p_of_l, 189);
    reorder_dcn_w_k<<<(4032*HEAD)/256, 256>>>(dcn_w, (bf16*)p_wt_h, (bf16*)p_wt_l);

    // id / off GEMMs: cat-mode implicit im2col
    gemm_tc_k<<<dim3(144, 1, BB), 256, GM_SMEM>>>((bf16*)p_id_h, (bf16*)p_id_l, fTh, fTl,
        zImg, kImg, 2, osH, 4032, HEAD, id_b1, bn_g, bn_b, bn_m, bn_v, 0, 1, id1);
    gemm_tc_k<<<dim3(144, 1, BB), 256, GM_SMEM>>>((bf16*)p_of_h, (bf16*)p_of_l, fTh, fTl,
        zImg, kImg, 2, (long)189*P, 4032, 189, off_b, bn_g, bn_b, bn_m, bn_v, 0, 0, offv);

    // DCN gather + GEMM (explicit B, BN + relu fused)
    dcn_cols_k<<<dim3(P/256, 63, BB), 256>>>(featT, offv, colsh, colsl);
    gemm_tc_k<<<dim3(144, 1, BB), 256, GM_SMEM>>>((bf16*)p_wt_h, (bf16*)p_wt_l, colsh, colsl,
        (long)P*4032, 0, 0, osH, 4032, HEAD, dcn_b, bn_g, bn_b, bn_m, bn_v, 1, 1, dv);

    // 1x1 heads -> output regions (hm, bz, idout, owh)
    float* out_hm  = out;
    float* out_bz  = out + (long)BB*24*P;
    float* out_id  = out_bz + (long)BB*16*P;
    float* out_owh = out_id + (long)BB*128*P;

    conv1x1_k<24><<<dim3(18, BB, 1), 256>>>(hm1, hm_w2, hm_b2, out_hm, 24, 0);
    conv1x1_k<16><<<dim3(18, BB, 1), 256>>>(dv,  bz_w,  bz_b,  out_bz, 16, 0);
    conv1x1_k<32><<<dim3(18, BB, 4), 256>>>(id1, id_w2, id_b2, out_id, 128, 0);
    conv1x1_k<2> <<<dim3(18, 28, 1), 256>>>(wh1, wh_w2, wh_b2, out_owh, 2, 1);
}